// round 1
// baseline (speedup 1.0000x reference)
#include <cuda_runtime.h>
#include <math.h>

#define NB 2
#define NC 256
#define NS 32768
#define CTX 77
#define CDIM 768
#define HEADS 8
#define HD 32
#define JP 80
#define NP 640          // padded (h,j) dimension: 8*80
#define M_TOTAL 65536   // NB * NS
#define EPS 1e-5f
#define ATT_SCALE 0.17677669529663687f  // 1/sqrt(32)

// ---------------- scratch (static device globals; no allocation) ----------------
__device__ float g_part[1024][2];
__device__ float g_stat[16][2];                 // mean, rstd per (b*8+g)
__device__ float g_k[NB * HEADS * CTX * HD];    // [b][h][j][d]  (scale folded in)
__device__ float g_v[NB * HEADS * CTX * HD];
__device__ float g_kp[NB * NC * NP];            // K' : [b][c][n]
__device__ float g_vw[NB * NP * NC];            // VW : [b][n][c]
__device__ float g_s[(size_t)M_TOTAL * NP];     // scores / probs [row][n]

// ---------------- K1a: groupnorm partial sums ----------------
// grid 1024 (16 group-chunks * 64 parts), block 256. Each chunk is contiguous 1M floats.
__global__ void gn_partial_k(const float* __restrict__ x) {
    int tid = threadIdx.x, blk = blockIdx.x;
    const float4* p = (const float4*)x + (size_t)blk * 4096;
    float s = 0.f, sq = 0.f;
#pragma unroll
    for (int i = 0; i < 16; i++) {
        float4 v = p[i * 256 + tid];
        s  += v.x + v.y + v.z + v.w;
        sq += v.x * v.x + v.y * v.y + v.z * v.z + v.w * v.w;
    }
#pragma unroll
    for (int o = 16; o; o >>= 1) {
        s  += __shfl_xor_sync(0xffffffffu, s, o);
        sq += __shfl_xor_sync(0xffffffffu, sq, o);
    }
    __shared__ float r[8][2];
    if ((tid & 31) == 0) { r[tid >> 5][0] = s; r[tid >> 5][1] = sq; }
    __syncthreads();
    if (tid == 0) {
        float ts = 0.f, tq = 0.f;
#pragma unroll
        for (int i = 0; i < 8; i++) { ts += r[i][0]; tq += r[i][1]; }
        g_part[blk][0] = ts; g_part[blk][1] = tq;
    }
}

// ---------------- K1b: finalize stats ----------------
__global__ void gn_final_k() {
    int gi = blockIdx.x, t = threadIdx.x;   // 16 blocks, 32 threads
    float s  = g_part[gi * 64 + t][0] + g_part[gi * 64 + 32 + t][0];
    float sq = g_part[gi * 64 + t][1] + g_part[gi * 64 + 32 + t][1];
#pragma unroll
    for (int o = 16; o; o >>= 1) {
        s  += __shfl_xor_sync(0xffffffffu, s, o);
        sq += __shfl_xor_sync(0xffffffffu, sq, o);
    }
    if (t == 0) {
        const float inv = 1.f / 1048576.f;
        float mean = s * inv;
        float var  = sq * inv - mean * mean;
        g_stat[gi][0] = mean;
        g_stat[gi][1] = rsqrtf(var + EPS);
    }
}

// ---------------- K2: context LayerNorm + K,V projection ----------------
// grid 154 (= 2*77), block 256.
__global__ void ctx_kv_k(const float* __restrict__ ctx, const float* __restrict__ lng,
                         const float* __restrict__ lnb, const float* __restrict__ Wk,
                         const float* __restrict__ Wv) {
    __shared__ float xn[768];
    __shared__ float red[8][2];
    __shared__ float smean, srstd;
    int row = blockIdx.x, tid = threadIdx.x;
    const float* cp = ctx + (size_t)row * 768;
    float v[3]; float s = 0.f, sq = 0.f;
#pragma unroll
    for (int i = 0; i < 3; i++) { v[i] = cp[tid + i * 256]; s += v[i]; sq += v[i] * v[i]; }
#pragma unroll
    for (int o = 16; o; o >>= 1) {
        s  += __shfl_xor_sync(0xffffffffu, s, o);
        sq += __shfl_xor_sync(0xffffffffu, sq, o);
    }
    if ((tid & 31) == 0) { red[tid >> 5][0] = s; red[tid >> 5][1] = sq; }
    __syncthreads();
    if (tid == 0) {
        float ts = 0.f, tq = 0.f;
#pragma unroll
        for (int i = 0; i < 8; i++) { ts += red[i][0]; tq += red[i][1]; }
        float mean = ts * (1.f / 768.f);
        float var  = tq * (1.f / 768.f) - mean * mean;
        smean = mean; srstd = rsqrtf(var + EPS);
    }
    __syncthreads();
    float mean = smean, rstd = srstd;
#pragma unroll
    for (int i = 0; i < 3; i++) {
        int idx = tid + i * 256;
        xn[idx] = (v[i] - mean) * rstd * lng[idx] + lnb[idx];
    }
    __syncthreads();
    float ak = 0.f, av = 0.f;
    for (int i = 0; i < 768; i++) {
        float xv = xn[i];
        ak += xv * Wk[i * 256 + tid];
        av += xv * Wv[i * 256 + tid];
    }
    int b = row / 77, j = row % 77;
    int h = tid >> 5, d = tid & 31;
    size_t o = (((size_t)b * HEADS + h) * CTX + j) * HD + d;
    g_k[o] = ak * ATT_SCALE;   // fold attention scale into K
    g_v[o] = av;
}

// ---------------- K2b: K'[b][c][n] = sum_d Wq[c][h*32+d] * K[b,h,j,d] ----------------
// grid (640, 2), block 256 (thread = c). Pad columns j>=77 are zero.
__global__ void make_kp_k(const float* __restrict__ Wq) {
    int n = blockIdx.x, b = blockIdx.y, c = threadIdx.x;
    int h = n / JP, j = n % JP;
    __shared__ float wq[256][33];
    __shared__ float ks[32];
#pragma unroll
    for (int i = 0; i < 32; i++) {
        int r = i * 8 + (c >> 5); int d = c & 31;
        wq[r][d] = Wq[r * 256 + h * 32 + d];
    }
    if (c < 32 && j < CTX) ks[c] = g_k[(((size_t)b * HEADS + h) * CTX + j) * HD + c];
    __syncthreads();
    float acc = 0.f;
    if (j < CTX) {
#pragma unroll
        for (int d = 0; d < 32; d++) acc += wq[c][d] * ks[d];
    }
    g_kp[((size_t)b * NC + c) * NP + n] = acc;
}

// ---------------- K2c: VW[b][n][c] = sum_d V[b,h,j,d] * Wo[h*32+d][c] ----------------
__global__ void make_vw_k(const float* __restrict__ Wo) {
    int n = blockIdx.x, b = blockIdx.y, c = threadIdx.x;
    int h = n / JP, j = n % JP;
    __shared__ float vs[32];
    if (c < 32 && j < CTX) vs[c] = g_v[(((size_t)b * HEADS + h) * CTX + j) * HD + c];
    __syncthreads();
    float acc = 0.f;
    if (j < CTX) {
#pragma unroll
        for (int d = 0; d < 32; d++) acc += vs[d] * Wo[(h * 32 + d) * 256 + c];
    }
    g_vw[((size_t)b * NP + n) * NC + c] = acc;
}

// ---------------- K3: GEMM1  S = gn(x^T) @ K'   (M=65536, N=640, K=256) ----------------
// grid (10, 512): x-dim = N tiles (adjacent CTAs share the A tile -> L2 reuse)
__global__ void gemm1_k(const float* __restrict__ x, const float* __restrict__ gng,
                        const float* __restrict__ gnb) {
    __shared__ float As[16][128];
    __shared__ float Bs[16][64];
    __shared__ float cA[256], cB[256];
    int tid = threadIdx.x;
    int row0 = blockIdx.y * 128;
    int b = row0 >> 15, s0 = row0 & 32767;
    int n0 = blockIdx.x * 64;
    {   // per-channel groupnorm affine: a = v*cA[c] + cB[c]
        int c = tid; int g = c >> 5;
        float mean = g_stat[b * 8 + g][0], rstd = g_stat[b * 8 + g][1];
        float ga = gng[c], be = gnb[c];
        cA[c] = rstd * ga; cB[c] = be - mean * rstd * ga;
    }
    __syncthreads();
    int a_s = tid & 127, a_c = tid >> 7;
    int b_n = tid & 63,  b_k = tid >> 6;
    int tx = tid & 15,   ty = tid >> 4;
    const float* xb = x + (size_t)b * 8388608;
    const float* Bp = g_kp + (size_t)b * NC * NP + n0;
    float acc[8][4];
#pragma unroll
    for (int i = 0; i < 8; i++)
#pragma unroll
        for (int j2 = 0; j2 < 4; j2++) acc[i][j2] = 0.f;

    for (int k0 = 0; k0 < 256; k0 += 16) {
#pragma unroll
        for (int i = 0; i < 8; i++) {
            int c = k0 + a_c + 2 * i;
            float v = xb[(size_t)c * 32768 + s0 + a_s];
            As[a_c + 2 * i][a_s] = v * cA[c] + cB[c];
        }
#pragma unroll
        for (int i = 0; i < 4; i++) {
            int k = b_k + 4 * i;
            Bs[k][b_n] = Bp[(size_t)(k0 + k) * NP + b_n];
        }
        __syncthreads();
#pragma unroll
        for (int k = 0; k < 16; k++) {
            float4 a0 = *(const float4*)&As[k][ty * 8];
            float4 a1 = *(const float4*)&As[k][ty * 8 + 4];
            float4 bb = *(const float4*)&Bs[k][tx * 4];
            float am[8] = {a0.x, a0.y, a0.z, a0.w, a1.x, a1.y, a1.z, a1.w};
            float bn[4] = {bb.x, bb.y, bb.z, bb.w};
#pragma unroll
            for (int i = 0; i < 8; i++)
#pragma unroll
                for (int j2 = 0; j2 < 4; j2++) acc[i][j2] += am[i] * bn[j2];
        }
        __syncthreads();
    }
#pragma unroll
    for (int i = 0; i < 8; i++) {
        int row = row0 + ty * 8 + i;
        float4 st = make_float4(acc[i][0], acc[i][1], acc[i][2], acc[i][3]);
        *(float4*)&g_s[(size_t)row * NP + n0 + tx * 4] = st;
    }
}

// ---------------- K4: in-place row softmax over each 77-key segment ----------------
// grid 8192, block 256; one warp per (row, head) task, 8 tasks per warp.
__global__ void softmax_k() {
    int warp = threadIdx.x >> 5, lane = threadIdx.x & 31;
#pragma unroll
    for (int it = 0; it < 8; it++) {
        int task = blockIdx.x * 64 + warp * 8 + it;
        int row = task >> 3, h = task & 7;
        float* p = &g_s[(size_t)row * NP + h * JP];
        float v0 = p[lane];
        float v1 = p[lane + 32];
        float v2 = (lane + 64 < CTX) ? p[lane + 64] : -INFINITY;
        float m = fmaxf(v0, fmaxf(v1, v2));
#pragma unroll
        for (int o = 16; o; o >>= 1) m = fmaxf(m, __shfl_xor_sync(0xffffffffu, m, o));
        float e0 = __expf(v0 - m), e1 = __expf(v1 - m), e2 = __expf(v2 - m);
        float s = e0 + e1 + e2;
#pragma unroll
        for (int o = 16; o; o >>= 1) s += __shfl_xor_sync(0xffffffffu, s, o);
        float inv = 1.f / s;
        p[lane] = e0 * inv;
        p[lane + 32] = e1 * inv;
        if (lane < 16) p[lane + 64] = e2 * inv;  // zeros the 3 pad slots (e2=0 there)
    }
}

// ---------------- K5: GEMM2  out = P @ VW + bo + x  (M=65536, N=256, K=640) ----------------
// Transposed store through smem: d_out layout is [b][c][s].
__global__ void gemm2_k(const float* __restrict__ x, const float* __restrict__ bo,
                        float* __restrict__ out) {
    __shared__ float sm[8320];                         // 128*65 floats (reused)
    float (*As)[132] = (float(*)[132])sm;              // 16*132 = 2112 floats
    float (*Bs)[64]  = (float(*)[64])(sm + 2112);      // 16*64  = 1024 floats
    int tid = threadIdx.x;
    int row0 = blockIdx.y * 128;
    int b = row0 >> 15, s0 = row0 & 32767;
    int n0 = blockIdx.x * 64;
    int f4 = tid & 3, rr = tid >> 2;
    int b_n = tid & 63, b_k = tid >> 6;
    int tx = tid & 15, ty = tid >> 4;
    const float* Bp = g_vw + (size_t)b * NP * NC + n0;
    float acc[8][4];
#pragma unroll
    for (int i = 0; i < 8; i++)
#pragma unroll
        for (int j2 = 0; j2 < 4; j2++) acc[i][j2] = 0.f;

    for (int k0 = 0; k0 < NP; k0 += 16) {
#pragma unroll
        for (int i = 0; i < 2; i++) {
            int m = rr + i * 64;
            float4 v = *(const float4*)&g_s[(size_t)(row0 + m) * NP + k0 + f4 * 4];
            As[f4 * 4 + 0][m] = v.x; As[f4 * 4 + 1][m] = v.y;
            As[f4 * 4 + 2][m] = v.z; As[f4 * 4 + 3][m] = v.w;
        }
#pragma unroll
        for (int i = 0; i < 4; i++) {
            int k = b_k + 4 * i;
            Bs[k][b_n] = Bp[(size_t)(k0 + k) * NC + b_n];
        }
        __syncthreads();
#pragma unroll
        for (int k = 0; k < 16; k++) {
            float4 a0 = *(const float4*)&As[k][ty * 8];
            float4 a1 = *(const float4*)&As[k][ty * 8 + 4];
            float4 bb = *(const float4*)&Bs[k][tx * 4];
            float am[8] = {a0.x, a0.y, a0.z, a0.w, a1.x, a1.y, a1.z, a1.w};
            float bn[4] = {bb.x, bb.y, bb.z, bb.w};
#pragma unroll
            for (int i = 0; i < 8; i++)
#pragma unroll
                for (int j2 = 0; j2 < 4; j2++) acc[i][j2] += am[i] * bn[j2];
        }
        __syncthreads();
    }
    // transpose tile through smem, then coalesced store along s with residual + bias
    __syncthreads();
#pragma unroll
    for (int i = 0; i < 8; i++) {
        int m = ty * 8 + i;
#pragma unroll
        for (int j2 = 0; j2 < 4; j2++) sm[m * 65 + tx * 4 + j2] = acc[i][j2];
    }
    __syncthreads();
    const float* xb = x + (size_t)b * 8388608;
    float* ob = out + (size_t)b * 8388608;
#pragma unroll
    for (int it = 0; it < 32; it++) {
        int cl = (tid >> 7) + it * 2;   // 0..63
        int sl = tid & 127;
        int c = n0 + cl;
        size_t idx = (size_t)c * 32768 + s0 + sl;
        ob[idx] = sm[sl * 65 + cl] + bo[c] + xb[idx];
    }
}

// ---------------- launch ----------------
extern "C" void kernel_launch(void* const* d_in, const int* in_sizes, int n_in,
                              void* d_out, int out_size) {
    const float* x    = (const float*)d_in[0];
    const float* ctx  = (const float*)d_in[1];
    const float* gng  = (const float*)d_in[2];
    const float* gnb  = (const float*)d_in[3];
    const float* lng  = (const float*)d_in[4];
    const float* lnb  = (const float*)d_in[5];
    const float* Wq   = (const float*)d_in[6];
    const float* Wk   = (const float*)d_in[7];
    const float* Wv   = (const float*)d_in[8];
    const float* Wo   = (const float*)d_in[9];
    const float* bo   = (const float*)d_in[10];
    float* out = (float*)d_out;

    gn_partial_k<<<1024, 256>>>(x);
    gn_final_k<<<16, 32>>>();
    ctx_kv_k<<<154, 256>>>(ctx, lng, lnb, Wk, Wv);
    make_kp_k<<<dim3(NP, NB), 256>>>(Wq);
    make_vw_k<<<dim3(NP, NB), 256>>>(Wo);
    gemm1_k<<<dim3(NP / 64, M_TOTAL / 128), 256>>>(x, gng, gnb);
    softmax_k<<<8192, 256>>>();
    gemm2_k<<<dim3(NC / 64, M_TOTAL / 128), 256>>>(x, bo, out);
}

// round 4
// speedup vs baseline: 1.6820x; 1.6820x over previous
#include <cuda_runtime.h>
#include <math.h>
#include <stdint.h>

#define NB 2
#define NC 256
#define NS 32768
#define CTX 77
#define HEADS 8
#define JP 80
#define NP 640
#define M_TOTAL 65536
#define EPS 1e-5f
#define ATT_SCALE 0.17677669529663687f

// ---------------- scratch ----------------
__device__ float g_part[1024][2];
__device__ float g_stat[16][2];
__device__ float g_k[NB * HEADS * CTX * 32];
__device__ float g_v[NB * HEADS * CTX * 32];
__device__ float g_kp[NB * NP * NC];            // B1: [b][n][k=c], tf32-rounded
__device__ float g_vw[NB * NC * NP];            // B2: [b][c][k=np], tf32-rounded
__device__ float g_xt[(size_t)M_TOTAL * NC];    // A1: [row][c], tf32-rounded
__device__ float g_s[(size_t)M_TOTAL * NP];     // logits [row][n]
__device__ float g_rs[(size_t)M_TOTAL * 16];    // per (row,head): max, 1/sum

// ---------------- helpers ----------------
__device__ __forceinline__ float to_tf32(float f) {
    float o; asm("cvt.rna.tf32.f32 %0, %1;" : "=f"(o) : "f"(f)); return o;
}
__device__ __forceinline__ uint32_t tf32_bits(float f) {
    uint32_t u; asm("cvt.rna.tf32.f32 %0, %1;" : "=r"(u) : "f"(f)); return u;
}
__device__ __forceinline__ uint32_t smem_u32(const void* p) {
    uint32_t a;
    asm("{ .reg .u64 t; cvta.to.shared.u64 t, %1; cvt.u32.u64 %0, t; }" : "=r"(a) : "l"(p));
    return a;
}
__device__ __forceinline__ void cp16(uint32_t dst, const void* src) {
    asm volatile("cp.async.ca.shared.global [%0], [%1], 16;" :: "r"(dst), "l"(src));
}
__device__ __forceinline__ void cp_commit() { asm volatile("cp.async.commit_group;" ::: "memory"); }
__device__ __forceinline__ void cp_wait0() { asm volatile("cp.async.wait_group 0;" ::: "memory"); }
__device__ __forceinline__ void cp_wait1() { asm volatile("cp.async.wait_group 1;" ::: "memory"); }

__device__ __forceinline__ void mma8(float* c, const uint32_t* a, uint32_t b0, uint32_t b1) {
    asm volatile("mma.sync.aligned.m16n8k8.row.col.f32.tf32.tf32.f32 "
                 "{%0,%1,%2,%3},{%4,%5,%6,%7},{%8,%9},{%0,%1,%2,%3};"
                 : "+f"(c[0]), "+f"(c[1]), "+f"(c[2]), "+f"(c[3])
                 : "r"(a[0]), "r"(a[1]), "r"(a[2]), "r"(a[3]), "r"(b0), "r"(b1));
}

#define SA 36            // smem row stride in floats (conflict-free)

// ---------------- K1a/K1b: groupnorm stats ----------------
__global__ void gn_partial_k(const float* __restrict__ x) {
    int tid = threadIdx.x, blk = blockIdx.x;
    const float4* p = (const float4*)x + (size_t)blk * 4096;
    float s = 0.f, sq = 0.f;
#pragma unroll
    for (int i = 0; i < 16; i++) {
        float4 v = p[i * 256 + tid];
        s += v.x + v.y + v.z + v.w;
        sq += v.x * v.x + v.y * v.y + v.z * v.z + v.w * v.w;
    }
#pragma unroll
    for (int o = 16; o; o >>= 1) {
        s += __shfl_xor_sync(0xffffffffu, s, o);
        sq += __shfl_xor_sync(0xffffffffu, sq, o);
    }
    __shared__ float r[8][2];
    if ((tid & 31) == 0) { r[tid >> 5][0] = s; r[tid >> 5][1] = sq; }
    __syncthreads();
    if (tid == 0) {
        float ts = 0.f, tq = 0.f;
#pragma unroll
        for (int i = 0; i < 8; i++) { ts += r[i][0]; tq += r[i][1]; }
        g_part[blk][0] = ts; g_part[blk][1] = tq;
    }
}

__global__ void gn_final_k() {
    int gi = blockIdx.x, t = threadIdx.x;
    float s = g_part[gi * 64 + t][0] + g_part[gi * 64 + 32 + t][0];
    float sq = g_part[gi * 64 + t][1] + g_part[gi * 64 + 32 + t][1];
#pragma unroll
    for (int o = 16; o; o >>= 1) {
        s += __shfl_xor_sync(0xffffffffu, s, o);
        sq += __shfl_xor_sync(0xffffffffu, sq, o);
    }
    if (t == 0) {
        const float inv = 1.f / 1048576.f;
        float mean = s * inv;
        float var = sq * inv - mean * mean;
        g_stat[gi][0] = mean;
        g_stat[gi][1] = rsqrtf(var + EPS);
    }
}

// ---------------- K1c: transpose + GN affine + tf32 round ----------------
__global__ void xt_k(const float* __restrict__ x, const float* __restrict__ gng,
                     const float* __restrict__ gnb) {
    __shared__ float tl[32][33];
    __shared__ float a32[32], b32[32];
    int tx = threadIdx.x, ty = threadIdx.y;
    int s0 = blockIdx.x * 32, c0 = blockIdx.y * 32, b = blockIdx.z;
    if (ty == 0) {
        int c = c0 + tx, g = c >> 5;
        float mean = g_stat[b * 8 + g][0], rstd = g_stat[b * 8 + g][1];
        float ga = gng[c];
        a32[tx] = rstd * ga;
        b32[tx] = gnb[c] - mean * rstd * ga;
    }
#pragma unroll
    for (int i = ty; i < 32; i += 8)
        tl[i][tx] = x[((size_t)b * 256 + c0 + i) * 32768 + s0 + tx];
    __syncthreads();
#pragma unroll
    for (int i = ty; i < 32; i += 8) {
        float v = tl[tx][i] * a32[tx] + b32[tx];
        g_xt[((size_t)b * 32768 + s0 + i) * 256 + c0 + tx] = to_tf32(v);
    }
}

// ---------------- K2: context LN + K,V projection ----------------
__global__ void ctx_kv_k(const float* __restrict__ ctx, const float* __restrict__ lng,
                         const float* __restrict__ lnb, const float* __restrict__ Wk,
                         const float* __restrict__ Wv) {
    __shared__ float xn[768];
    __shared__ float red[8][2];
    __shared__ float smean, srstd;
    int row = blockIdx.x, tid = threadIdx.x;
    const float* cp = ctx + (size_t)row * 768;
    float v[3]; float s = 0.f, sq = 0.f;
#pragma unroll
    for (int i = 0; i < 3; i++) { v[i] = cp[tid + i * 256]; s += v[i]; sq += v[i] * v[i]; }
#pragma unroll
    for (int o = 16; o; o >>= 1) {
        s += __shfl_xor_sync(0xffffffffu, s, o);
        sq += __shfl_xor_sync(0xffffffffu, sq, o);
    }
    if ((tid & 31) == 0) { red[tid >> 5][0] = s; red[tid >> 5][1] = sq; }
    __syncthreads();
    if (tid == 0) {
        float ts = 0.f, tq = 0.f;
#pragma unroll
        for (int i = 0; i < 8; i++) { ts += red[i][0]; tq += red[i][1]; }
        float mean = ts * (1.f / 768.f);
        float var = tq * (1.f / 768.f) - mean * mean;
        smean = mean; srstd = rsqrtf(var + EPS);
    }
    __syncthreads();
    float mean = smean, rstd = srstd;
#pragma unroll
    for (int i = 0; i < 3; i++) {
        int idx = tid + i * 256;
        xn[idx] = (v[i] - mean) * rstd * lng[idx] + lnb[idx];
    }
    __syncthreads();
    float ak = 0.f, av = 0.f;
    for (int i = 0; i < 768; i++) {
        float xv = xn[i];
        ak += xv * Wk[i * 256 + tid];
        av += xv * Wv[i * 256 + tid];
    }
    int b = row / 77, j = row % 77;
    int h = tid >> 5, d = tid & 31;
    size_t o = (((size_t)b * HEADS + h) * CTX + j) * 32 + d;
    g_k[o] = ak * ATT_SCALE;
    g_v[o] = av;
}

// ---------------- K2b: K'[b][n][k=c] tf32 ----------------
__global__ void make_kp_k(const float* __restrict__ Wq) {
    int n = blockIdx.x, b = blockIdx.y, c = threadIdx.x;
    int h = n / JP, j = n % JP;
    __shared__ float wq[256][33];
    __shared__ float ks[32];
#pragma unroll
    for (int i = 0; i < 32; i++) {
        int r = i * 8 + (c >> 5); int d = c & 31;
        wq[r][d] = Wq[r * 256 + h * 32 + d];
    }
    if (c < 32 && j < CTX) ks[c] = g_k[(((size_t)b * HEADS + h) * CTX + j) * 32 + c];
    __syncthreads();
    float acc = 0.f;
    if (j < CTX) {
#pragma unroll
        for (int d = 0; d < 32; d++) acc += wq[c][d] * ks[d];
    }
    g_kp[((size_t)b * NP + n) * NC + c] = to_tf32(acc);
}

// ---------------- K2c: VW[b][c][k=np] tf32 ----------------
__global__ void make_vw_k(const float* __restrict__ Wo) {
    int n = blockIdx.x, b = blockIdx.y, c = threadIdx.x;
    int h = n / JP, j = n % JP;
    __shared__ float vs[32];
    if (c < 32 && j < CTX) vs[c] = g_v[(((size_t)b * HEADS + h) * CTX + j) * 32 + c];
    __syncthreads();
    float acc = 0.f;
    if (j < CTX) {
#pragma unroll
        for (int d = 0; d < 32; d++) acc += vs[d] * Wo[(h * 32 + d) * 256 + c];
    }
    g_vw[((size_t)b * NC + c) * NP + n] = to_tf32(acc);
}

// ---------------- GEMM1: S = A1 @ B1^T (M=65536, N=640, K=256) ----------------
__global__ void __launch_bounds__(256) gemm1_mma() {
    extern __shared__ char smem[];
    uint32_t sb = smem_u32(smem);
    int tid = threadIdx.x, lane = tid & 31, wid = tid >> 5;
    int grp = lane >> 2, lt4 = lane & 3;
    int wm0 = (wid & 1) * 64, wn0 = (wid >> 1) * 32;
    int n0 = blockIdx.x * 128;
    int row0 = blockIdx.y * 128;
    int b = row0 >> 15;

    const float* Ag = g_xt + (size_t)row0 * 256;
    const float* Bg = g_kp + ((size_t)b * NP + n0) * 256;

    const uint32_t offA[2] = {0u, 2u * 18432u};
    const uint32_t offB[2] = {18432u, 3u * 18432u};

    int sm = tid >> 3;
    int sk = (tid & 7) * 4;

    auto stage = [&](int ki, int buf) {
#pragma unroll
        for (int i = 0; i < 4; i++) {
            int m = sm + i * 32;
            uint32_t d = ((uint32_t)m * SA + sk) * 4u;
            cp16(sb + offA[buf] + d, Ag + (size_t)m * 256 + ki * 32 + sk);
            cp16(sb + offB[buf] + d, Bg + (size_t)m * 256 + ki * 32 + sk);
        }
        cp_commit();
    };

    float acc[4][4][4];
#pragma unroll
    for (int a = 0; a < 4; a++)
#pragma unroll
        for (int c = 0; c < 4; c++)
#pragma unroll
            for (int e = 0; e < 4; e++) acc[a][c][e] = 0.f;

    stage(0, 0);
    const int NK = 8;
    for (int ki = 0; ki < NK; ki++) {
        int cur = ki & 1;
        if (ki + 1 < NK) { stage(ki + 1, cur ^ 1); cp_wait1(); } else { cp_wait0(); }
        __syncthreads();
        const uint32_t* Au = (const uint32_t*)(smem + offA[cur]);
        const uint32_t* Bu = (const uint32_t*)(smem + offB[cur]);
#pragma unroll
        for (int ks = 0; ks < 32; ks += 8) {
            uint32_t af[4][4];
#pragma unroll
            for (int mf = 0; mf < 4; mf++) {
                const uint32_t* p = Au + (wm0 + mf * 16 + grp) * SA + ks + lt4;
                af[mf][0] = p[0]; af[mf][1] = p[8 * SA];
                af[mf][2] = p[4]; af[mf][3] = p[8 * SA + 4];
            }
#pragma unroll
            for (int nf = 0; nf < 4; nf++) {
                const uint32_t* q = Bu + (wn0 + nf * 8 + grp) * SA + ks + lt4;
                uint32_t b0 = q[0], b1 = q[4];
#pragma unroll
                for (int mf = 0; mf < 4; mf++) mma8(acc[mf][nf], af[mf], b0, b1);
            }
        }
        __syncthreads();
    }

#pragma unroll
    for (int mf = 0; mf < 4; mf++) {
        int r = row0 + wm0 + mf * 16 + grp;
#pragma unroll
        for (int nf = 0; nf < 4; nf++) {
            int c = n0 + wn0 + nf * 8 + 2 * lt4;
            float2 v0 = make_float2(acc[mf][nf][0], acc[mf][nf][1]);
            float2 v1 = make_float2(acc[mf][nf][2], acc[mf][nf][3]);
            *(float2*)&g_s[(size_t)r * NP + c] = v0;
            *(float2*)&g_s[(size_t)(r + 8) * NP + c] = v1;
        }
    }
}

// ---------------- row stats ----------------
__global__ void rowstat_k() {
    int g = blockIdx.x * 256 + threadIdx.x;
    int row = g >> 3, h = g & 7;
    const float* p = &g_s[(size_t)row * NP + h * JP];
    float m = -1e30f;
    for (int j = 0; j < CTX; j++) m = fmaxf(m, p[j]);
    float s = 0.f;
    for (int j = 0; j < CTX; j++) s += __expf(p[j] - m);
    g_rs[(size_t)row * 16 + h * 2] = m;
    g_rs[(size_t)row * 16 + h * 2 + 1] = 1.f / s;
}

// ---------------- GEMM2: out = softmax(S) @ B2^T + bo + x ----------------
__global__ void __launch_bounds__(256) gemm2_mma(const float* __restrict__ x,
                                                 const float* __restrict__ bo,
                                                 float* __restrict__ out) {
    extern __shared__ char smem[];
    uint32_t sb = smem_u32(smem);
    int tid = threadIdx.x, lane = tid & 31, wid = tid >> 5;
    int grp = lane >> 2, lt4 = lane & 3;
    int wm0 = (wid & 1) * 64, wn0 = (wid >> 1) * 32;
    int n0 = blockIdx.x * 128;
    int row0 = blockIdx.y * 128;
    int b = row0 >> 15, s0 = row0 & 32767;

    float* sstat = (float*)smem;
    const uint32_t offA[2] = {8192u, 8192u + 2u * 18432u};
    const uint32_t offB[2] = {8192u + 18432u, 8192u + 3u * 18432u};

#pragma unroll
    for (int i = 0; i < 8; i++)
        sstat[tid + i * 256] = g_rs[(size_t)row0 * 16 + tid + i * 256];
    __syncthreads();   // FIX (R3 bug): sstat must be visible before prologue stsA

    const float* Ag = g_s + (size_t)row0 * NP;
    const float* Bg = g_vw + ((size_t)b * NC + n0) * NP;

    int sm = tid >> 3;
    int sk = (tid & 7) * 4;

    float4 ra[4];
    auto ldA = [&](int ki) {
        int kb = ki * 32 + sk;
#pragma unroll
        for (int i = 0; i < 4; i++)
            ra[i] = *(const float4*)(Ag + (size_t)(sm + i * 32) * NP + kb);
    };
    auto stsA = [&](int ki, int buf) {
        int kb = ki * 32 + sk;
        int h = kb / JP;
        int jj = kb - h * JP;
#pragma unroll
        for (int i = 0; i < 4; i++) {
            int m = sm + i * 32;
            float mx = sstat[m * 16 + 2 * h];
            float iv = sstat[m * 16 + 2 * h + 1];
            float4 v = ra[i];
            uint4 o;
            o.x = tf32_bits((jj + 0 < CTX) ? __expf(v.x - mx) * iv : 0.f);
            o.y = tf32_bits((jj + 1 < CTX) ? __expf(v.y - mx) * iv : 0.f);
            o.z = tf32_bits((jj + 2 < CTX) ? __expf(v.z - mx) * iv : 0.f);
            o.w = tf32_bits((jj + 3 < CTX) ? __expf(v.w - mx) * iv : 0.f);
            *(uint4*)(smem + offA[buf] + ((uint32_t)m * SA + sk) * 4u) = o;
        }
    };
    auto cpB = [&](int ki, int buf) {
        int kb = ki * 32 + sk;
#pragma unroll
        for (int i = 0; i < 4; i++) {
            int m = sm + i * 32;
            cp16(sb + offB[buf] + ((uint32_t)m * SA + sk) * 4u, Bg + (size_t)m * NP + kb);
        }
        cp_commit();
    };

    float acc[4][4][4];
#pragma unroll
    for (int a = 0; a < 4; a++)
#pragma unroll
        for (int c = 0; c < 4; c++)
#pragma unroll
            for (int e = 0; e < 4; e++) acc[a][c][e] = 0.f;

    ldA(0); cpB(0, 0); stsA(0, 0);

    const int NK = 20;
    for (int ki = 0; ki < NK; ki++) {
        int cur = ki & 1;
        if (ki + 1 < NK) { ldA(ki + 1); cpB(ki + 1, cur ^ 1); cp_wait1(); } else { cp_wait0(); }
        __syncthreads();
        const uint32_t* Au = (const uint32_t*)(smem + offA[cur]);
        const uint32_t* Bu = (const uint32_t*)(smem + offB[cur]);
#pragma unroll
        for (int ks = 0; ks < 32; ks += 8) {
            uint32_t af[4][4];
#pragma unroll
            for (int mf = 0; mf < 4; mf++) {
                const uint32_t* p = Au + (wm0 + mf * 16 + grp) * SA + ks + lt4;
                af[mf][0] = p[0]; af[mf][1] = p[8 * SA];
                af[mf][2] = p[4]; af[mf][3] = p[8 * SA + 4];
            }
#pragma unroll
            for (int nf = 0; nf < 4; nf++) {
                const uint32_t* q = Bu + (wn0 + nf * 8 + grp) * SA + ks + lt4;
                uint32_t b0 = q[0], b1 = q[4];
#pragma unroll
                for (int mf = 0; mf < 4; mf++) mma8(acc[mf][nf], af[mf], b0, b1);
            }
        }
        if (ki + 1 < NK) stsA(ki + 1, cur ^ 1);
        __syncthreads();
    }

    float* bounce = (float*)(smem + 8192);
#pragma unroll
    for (int mf = 0; mf < 4; mf++) {
        int r = wm0 + mf * 16 + grp;
#pragma unroll
        for (int nf = 0; nf < 4; nf++) {
            int c = wn0 + nf * 8 + 2 * lt4;
            bounce[(c + 0) * 132 + r] = acc[mf][nf][0];
            bounce[(c + 1) * 132 + r] = acc[mf][nf][1];
            bounce[(c + 0) * 132 + r + 8] = acc[mf][nf][2];
            bounce[(c + 1) * 132 + r + 8] = acc[mf][nf][3];
        }
    }
    __syncthreads();
#pragma unroll
    for (int pass = 0; pass < 16; pass++) {
        int c = pass * 8 + (tid >> 5);
        int cg = n0 + c;
        float4 v = *(const float4*)&bounce[c * 132 + lane * 4];
        size_t idx = ((size_t)b * 256 + cg) * 32768 + s0 + lane * 4;
        float4 xv = *(const float4*)(x + idx);
        float bb = bo[cg];
        v.x += xv.x + bb; v.y += xv.y + bb; v.z += xv.z + bb; v.w += xv.w + bb;
        *(float4*)(out + idx) = v;
    }
}

// ---------------- launch ----------------
extern "C" void kernel_launch(void* const* d_in, const int* in_sizes, int n_in,
                              void* d_out, int out_size) {
    const float* x   = (const float*)d_in[0];
    const float* ctx = (const float*)d_in[1];
    const float* gng = (const float*)d_in[2];
    const float* gnb = (const float*)d_in[3];
    const float* lng = (const float*)d_in[4];
    const float* lnb = (const float*)d_in[5];
    const float* Wq  = (const float*)d_in[6];
    const float* Wk  = (const float*)d_in[7];
    const float* Wv  = (const float*)d_in[8];
    const float* Wo  = (const float*)d_in[9];
    const float* bo  = (const float*)d_in[10];
    float* out = (float*)d_out;

    cudaFuncSetAttribute(gemm1_mma, cudaFuncAttributeMaxDynamicSharedMemorySize, 73728);
    cudaFuncSetAttribute(gemm2_mma, cudaFuncAttributeMaxDynamicSharedMemorySize, 81920);

    gn_partial_k<<<1024, 256>>>(x);
    gn_final_k<<<16, 32>>>();
    xt_k<<<dim3(1024, 8, 2), dim3(32, 8)>>>(x, gng, gnb);
    ctx_kv_k<<<154, 256>>>(ctx, lng, lnb, Wk, Wv);
    make_kp_k<<<dim3(NP, NB), 256>>>(Wq);
    make_vw_k<<<dim3(NP, NB), 256>>>(Wo);
    gemm1_mma<<<dim3(5, 512), 256, 73728>>>();
    rowstat_k<<<2048, 256>>>();
    gemm2_mma<<<dim3(2, 512), 256, 81920>>>(x, bo, out);
}

// round 5
// speedup vs baseline: 2.1135x; 1.2565x over previous
#include <cuda_runtime.h>
#include <math.h>
#include <stdint.h>

#define NB 2
#define NC 256
#define NS 32768
#define CTX 77
#define HEADS 8
#define JP 80
#define NP 640
#define M_TOTAL 65536
#define EPS 1e-5f
#define ATT_SCALE 0.17677669529663687f

// ---------------- scratch ----------------
__device__ float g_part[1024][2];
__device__ float g_stat[16][2];
__device__ float g_cn[NB * CTX * 768];          // normalized context
__device__ float g_k[NB * HEADS * CTX * 32];
__device__ float g_v[NB * HEADS * CTX * 32];
__device__ float g_kp[NB * NP * NC];            // B1: [b][n][k=c], tf32-rounded
__device__ float g_vw[NB * NC * NP];            // B2: [b][c][k=np], tf32-rounded
__device__ float g_xt[(size_t)M_TOTAL * NC];    // A1: [row][c], tf32-rounded
__device__ float g_s[(size_t)M_TOTAL * NP];     // logits [row][n]
__device__ float g_rs[(size_t)M_TOTAL * 16];    // per (row,head): max, 1/sum

// ---------------- helpers ----------------
__device__ __forceinline__ float to_tf32(float f) {
    float o; asm("cvt.rna.tf32.f32 %0, %1;" : "=f"(o) : "f"(f)); return o;
}
__device__ __forceinline__ uint32_t tf32_bits(float f) {
    uint32_t u; asm("cvt.rna.tf32.f32 %0, %1;" : "=r"(u) : "f"(f)); return u;
}
__device__ __forceinline__ uint32_t smem_u32(const void* p) {
    uint32_t a;
    asm("{ .reg .u64 t; cvta.to.shared.u64 t, %1; cvt.u32.u64 %0, t; }" : "=r"(a) : "l"(p));
    return a;
}
__device__ __forceinline__ void cp16(uint32_t dst, const void* src) {
    asm volatile("cp.async.ca.shared.global [%0], [%1], 16;" :: "r"(dst), "l"(src));
}
__device__ __forceinline__ void cp_commit() { asm volatile("cp.async.commit_group;" ::: "memory"); }
__device__ __forceinline__ void cp_wait0() { asm volatile("cp.async.wait_group 0;" ::: "memory"); }
__device__ __forceinline__ void cp_wait1() { asm volatile("cp.async.wait_group 1;" ::: "memory"); }

__device__ __forceinline__ void mma8(float* c, const uint32_t* a, uint32_t b0, uint32_t b1) {
    asm volatile("mma.sync.aligned.m16n8k8.row.col.f32.tf32.tf32.f32 "
                 "{%0,%1,%2,%3},{%4,%5,%6,%7},{%8,%9},{%0,%1,%2,%3};"
                 : "+f"(c[0]), "+f"(c[1]), "+f"(c[2]), "+f"(c[3])
                 : "r"(a[0]), "r"(a[1]), "r"(a[2]), "r"(a[3]), "r"(b0), "r"(b1));
}

#define SA 36            // smem row stride in floats (conflict-free)

// ---------------- K1a/K1b: groupnorm stats ----------------
__global__ void gn_partial_k(const float* __restrict__ x) {
    int tid = threadIdx.x, blk = blockIdx.x;
    const float4* p = (const float4*)x + (size_t)blk * 4096;
    float s = 0.f, sq = 0.f;
#pragma unroll
    for (int i = 0; i < 16; i++) {
        float4 v = p[i * 256 + tid];
        s += v.x + v.y + v.z + v.w;
        sq += v.x * v.x + v.y * v.y + v.z * v.z + v.w * v.w;
    }
#pragma unroll
    for (int o = 16; o; o >>= 1) {
        s += __shfl_xor_sync(0xffffffffu, s, o);
        sq += __shfl_xor_sync(0xffffffffu, sq, o);
    }
    __shared__ float r[8][2];
    if ((tid & 31) == 0) { r[tid >> 5][0] = s; r[tid >> 5][1] = sq; }
    __syncthreads();
    if (tid == 0) {
        float ts = 0.f, tq = 0.f;
#pragma unroll
        for (int i = 0; i < 8; i++) { ts += r[i][0]; tq += r[i][1]; }
        g_part[blk][0] = ts; g_part[blk][1] = tq;
    }
}

__global__ void gn_final_k() {
    int gi = blockIdx.x, t = threadIdx.x;
    float s = g_part[gi * 64 + t][0] + g_part[gi * 64 + 32 + t][0];
    float sq = g_part[gi * 64 + t][1] + g_part[gi * 64 + 32 + t][1];
#pragma unroll
    for (int o = 16; o; o >>= 1) {
        s += __shfl_xor_sync(0xffffffffu, s, o);
        sq += __shfl_xor_sync(0xffffffffu, sq, o);
    }
    if (t == 0) {
        const float inv = 1.f / 1048576.f;
        float mean = s * inv;
        float var = sq * inv - mean * mean;
        g_stat[gi][0] = mean;
        g_stat[gi][1] = rsqrtf(var + EPS);
    }
}

// ---------------- K1c: transpose + GN affine + tf32 round ----------------
__global__ void xt_k(const float* __restrict__ x, const float* __restrict__ gng,
                     const float* __restrict__ gnb) {
    __shared__ float tl[32][33];
    __shared__ float a32[32], b32[32];
    int tx = threadIdx.x, ty = threadIdx.y;
    int s0 = blockIdx.x * 32, c0 = blockIdx.y * 32, b = blockIdx.z;
    if (ty == 0) {
        int c = c0 + tx, g = c >> 5;
        float mean = g_stat[b * 8 + g][0], rstd = g_stat[b * 8 + g][1];
        float ga = gng[c];
        a32[tx] = rstd * ga;
        b32[tx] = gnb[c] - mean * rstd * ga;
    }
#pragma unroll
    for (int i = ty; i < 32; i += 8)
        tl[i][tx] = x[((size_t)b * 256 + c0 + i) * 32768 + s0 + tx];
    __syncthreads();
#pragma unroll
    for (int i = ty; i < 32; i += 8) {
        float v = tl[tx][i] * a32[tx] + b32[tx];
        g_xt[((size_t)b * 32768 + s0 + i) * 256 + c0 + tx] = to_tf32(v);
    }
}

// ---------------- K2a: context LayerNorm -> g_cn ----------------
__global__ void ctx_ln_k(const float* __restrict__ ctx, const float* __restrict__ lng,
                         const float* __restrict__ lnb) {
    __shared__ float red[8][2];
    __shared__ float smean, srstd;
    int row = blockIdx.x, tid = threadIdx.x;
    const float* cp = ctx + (size_t)row * 768;
    float v[3]; float s = 0.f, sq = 0.f;
#pragma unroll
    for (int i = 0; i < 3; i++) { v[i] = cp[tid + i * 256]; s += v[i]; sq += v[i] * v[i]; }
#pragma unroll
    for (int o = 16; o; o >>= 1) {
        s += __shfl_xor_sync(0xffffffffu, s, o);
        sq += __shfl_xor_sync(0xffffffffu, sq, o);
    }
    if ((tid & 31) == 0) { red[tid >> 5][0] = s; red[tid >> 5][1] = sq; }
    __syncthreads();
    if (tid == 0) {
        float ts = 0.f, tq = 0.f;
#pragma unroll
        for (int i = 0; i < 8; i++) { ts += red[i][0]; tq += red[i][1]; }
        float mean = ts * (1.f / 768.f);
        float var = tq * (1.f / 768.f) - mean * mean;
        smean = mean; srstd = rsqrtf(var + EPS);
    }
    __syncthreads();
    float mean = smean, rstd = srstd;
#pragma unroll
    for (int i = 0; i < 3; i++) {
        int idx = tid + i * 256;
        g_cn[(size_t)row * 768 + idx] = (v[i] - mean) * rstd * lng[idx] + lnb[idx];
    }
}

// ---------------- K2a': K,V projection (grid (4, 154), 128 thr) ----------------
__global__ void kv_proj_k(const float* __restrict__ Wk, const float* __restrict__ Wv) {
    __shared__ float xn[768];
    int tid = threadIdx.x, row = blockIdx.y;
#pragma unroll
    for (int i = 0; i < 6; i++) xn[tid + i * 128] = g_cn[(size_t)row * 768 + tid + i * 128];
    __syncthreads();
    int isV = tid >> 6;
    int c = blockIdx.x * 64 + (tid & 63);
    const float* W = isV ? Wv : Wk;
    float acc = 0.f;
#pragma unroll 16
    for (int i = 0; i < 768; i++) acc += xn[i] * W[i * 256 + c];
    int b = row / 77, j = row % 77, h = c >> 5, d = c & 31;
    size_t o = (((size_t)b * HEADS + h) * CTX + j) * 32 + d;
    if (isV) g_v[o] = acc;
    else g_k[o] = acc * ATT_SCALE;
}

// ---------------- K2b: K'[b][n][k=c] tf32 ----------------
__global__ void make_kp_k(const float* __restrict__ Wq) {
    int n = blockIdx.x, b = blockIdx.y, c = threadIdx.x;
    int h = n / JP, j = n % JP;
    __shared__ float wq[256][33];
    __shared__ float ks[32];
#pragma unroll
    for (int i = 0; i < 32; i++) {
        int r = i * 8 + (c >> 5); int d = c & 31;
        wq[r][d] = Wq[r * 256 + h * 32 + d];
    }
    if (c < 32 && j < CTX) ks[c] = g_k[(((size_t)b * HEADS + h) * CTX + j) * 32 + c];
    __syncthreads();
    float acc = 0.f;
    if (j < CTX) {
#pragma unroll
        for (int d = 0; d < 32; d++) acc += wq[c][d] * ks[d];
    }
    g_kp[((size_t)b * NP + n) * NC + c] = to_tf32(acc);
}

// ---------------- K2c: VW[b][c][k=np] tf32 ----------------
__global__ void make_vw_k(const float* __restrict__ Wo) {
    int n = blockIdx.x, b = blockIdx.y, c = threadIdx.x;
    int h = n / JP, j = n % JP;
    __shared__ float vs[32];
    if (c < 32 && j < CTX) vs[c] = g_v[(((size_t)b * HEADS + h) * CTX + j) * 32 + c];
    __syncthreads();
    float acc = 0.f;
    if (j < CTX) {
#pragma unroll
        for (int d = 0; d < 32; d++) acc += vs[d] * Wo[(h * 32 + d) * 256 + c];
    }
    g_vw[((size_t)b * NC + c) * NP + n] = to_tf32(acc);
}

// ---------------- GEMM1: S = A1 @ B1^T (M=65536, N=640, K=256) ----------------
__global__ void __launch_bounds__(256) gemm1_mma() {
    extern __shared__ char smem[];
    uint32_t sb = smem_u32(smem);
    int tid = threadIdx.x, lane = tid & 31, wid = tid >> 5;
    int grp = lane >> 2, lt4 = lane & 3;
    int wm0 = (wid & 1) * 64, wn0 = (wid >> 1) * 32;
    int n0 = blockIdx.x * 128;
    int row0 = blockIdx.y * 128;
    int b = row0 >> 15;

    const float* Ag = g_xt + (size_t)row0 * 256;
    const float* Bg = g_kp + ((size_t)b * NP + n0) * 256;

    const uint32_t offA[2] = {0u, 2u * 18432u};
    const uint32_t offB[2] = {18432u, 3u * 18432u};

    int sm = tid >> 3;
    int sk = (tid & 7) * 4;

    auto stage = [&](int ki, int buf) {
#pragma unroll
        for (int i = 0; i < 4; i++) {
            int m = sm + i * 32;
            uint32_t d = ((uint32_t)m * SA + sk) * 4u;
            cp16(sb + offA[buf] + d, Ag + (size_t)m * 256 + ki * 32 + sk);
            cp16(sb + offB[buf] + d, Bg + (size_t)m * 256 + ki * 32 + sk);
        }
        cp_commit();
    };

    float acc[4][4][4];
#pragma unroll
    for (int a = 0; a < 4; a++)
#pragma unroll
        for (int c = 0; c < 4; c++)
#pragma unroll
            for (int e = 0; e < 4; e++) acc[a][c][e] = 0.f;

    stage(0, 0);
    const int NK = 8;
    for (int ki = 0; ki < NK; ki++) {
        int cur = ki & 1;
        if (ki + 1 < NK) { stage(ki + 1, cur ^ 1); cp_wait1(); } else { cp_wait0(); }
        __syncthreads();
        const uint32_t* Au = (const uint32_t*)(smem + offA[cur]);
        const uint32_t* Bu = (const uint32_t*)(smem + offB[cur]);
#pragma unroll
        for (int ks = 0; ks < 32; ks += 8) {
            uint32_t af[4][4];
#pragma unroll
            for (int mf = 0; mf < 4; mf++) {
                const uint32_t* p = Au + (wm0 + mf * 16 + grp) * SA + ks + lt4;
                af[mf][0] = p[0]; af[mf][1] = p[8 * SA];
                af[mf][2] = p[4]; af[mf][3] = p[8 * SA + 4];
            }
#pragma unroll
            for (int nf = 0; nf < 4; nf++) {
                const uint32_t* q = Bu + (wn0 + nf * 8 + grp) * SA + ks + lt4;
                uint32_t b0 = q[0], b1 = q[4];
#pragma unroll
                for (int mf = 0; mf < 4; mf++) mma8(acc[mf][nf], af[mf], b0, b1);
            }
        }
        __syncthreads();
    }

#pragma unroll
    for (int mf = 0; mf < 4; mf++) {
        int r = row0 + wm0 + mf * 16 + grp;
#pragma unroll
        for (int nf = 0; nf < 4; nf++) {
            int c = n0 + wn0 + nf * 8 + 2 * lt4;
            float2 v0 = make_float2(acc[mf][nf][0], acc[mf][nf][1]);
            float2 v1 = make_float2(acc[mf][nf][2], acc[mf][nf][3]);
            *(float2*)&g_s[(size_t)r * NP + c] = v0;
            *(float2*)&g_s[(size_t)(r + 8) * NP + c] = v1;
        }
    }
}

// ---------------- row stats: warp per (row, head), coalesced ----------------
__global__ void rowstat_k() {
    int warp = threadIdx.x >> 5, lane = threadIdx.x & 31;
#pragma unroll
    for (int it = 0; it < 8; it++) {
        int task = blockIdx.x * 64 + warp * 8 + it;
        int row = task >> 3, h = task & 7;
        const float* p = &g_s[(size_t)row * NP + h * JP];
        float v0 = p[lane];
        float v1 = p[lane + 32];
        float v2 = (lane < 13) ? p[lane + 64] : -1e30f;
        float m = fmaxf(v0, fmaxf(v1, v2));
#pragma unroll
        for (int o = 16; o; o >>= 1) m = fmaxf(m, __shfl_xor_sync(0xffffffffu, m, o));
        float s = __expf(v0 - m) + __expf(v1 - m) + ((lane < 13) ? __expf(v2 - m) : 0.f);
#pragma unroll
        for (int o = 16; o; o >>= 1) s += __shfl_xor_sync(0xffffffffu, s, o);
        if (lane == 0)
            *(float2*)&g_rs[(size_t)row * 16 + h * 2] = make_float2(m, 1.f / s);
    }
}

// ---------------- GEMM2: out = softmax(S) @ B2^T + bo + x ----------------
__global__ void __launch_bounds__(256) gemm2_mma(const float* __restrict__ x,
                                                 const float* __restrict__ bo,
                                                 float* __restrict__ out) {
    extern __shared__ char smem[];
    uint32_t sb = smem_u32(smem);
    int tid = threadIdx.x, lane = tid & 31, wid = tid >> 5;
    int grp = lane >> 2, lt4 = lane & 3;
    int wm0 = (wid & 1) * 64, wn0 = (wid >> 1) * 32;
    int n0 = blockIdx.x * 128;
    int row0 = blockIdx.y * 128;
    int b = row0 >> 15, s0 = row0 & 32767;

    float* sstat = (float*)smem;
    const uint32_t offA[2] = {8192u, 8192u + 2u * 18432u};
    const uint32_t offB[2] = {8192u + 18432u, 8192u + 3u * 18432u};

#pragma unroll
    for (int i = 0; i < 8; i++)
        sstat[tid + i * 256] = g_rs[(size_t)row0 * 16 + tid + i * 256];
    __syncthreads();

    const float* Ag = g_s + (size_t)row0 * NP;
    const float* Bg = g_vw + ((size_t)b * NC + n0) * NP;

    int sm = tid >> 3;
    int sk = (tid & 7) * 4;

    float4 ra[4];
    auto ldA = [&](int ki) {
        int kb = ki * 32 + sk;
#pragma unroll
        for (int i = 0; i < 4; i++)
            ra[i] = *(const float4*)(Ag + (size_t)(sm + i * 32) * NP + kb);
    };
    auto stsA = [&](int ki, int buf) {
        int kb = ki * 32 + sk;
        int h = kb / JP;
        int jj = kb - h * JP;
#pragma unroll
        for (int i = 0; i < 4; i++) {
            int m = sm + i * 32;
            float mx = sstat[m * 16 + 2 * h];
            float iv = sstat[m * 16 + 2 * h + 1];
            float4 v = ra[i];
            uint4 o;
            o.x = tf32_bits((jj + 0 < CTX) ? __expf(v.x - mx) * iv : 0.f);
            o.y = tf32_bits((jj + 1 < CTX) ? __expf(v.y - mx) * iv : 0.f);
            o.z = tf32_bits((jj + 2 < CTX) ? __expf(v.z - mx) * iv : 0.f);
            o.w = tf32_bits((jj + 3 < CTX) ? __expf(v.w - mx) * iv : 0.f);
            *(uint4*)(smem + offA[buf] + ((uint32_t)m * SA + sk) * 4u) = o;
        }
    };
    auto cpB = [&](int ki, int buf) {
        int kb = ki * 32 + sk;
#pragma unroll
        for (int i = 0; i < 4; i++) {
            int m = sm + i * 32;
            cp16(sb + offB[buf] + ((uint32_t)m * SA + sk) * 4u, Bg + (size_t)m * NP + kb);
        }
        cp_commit();
    };

    float acc[4][4][4];
#pragma unroll
    for (int a = 0; a < 4; a++)
#pragma unroll
        for (int c = 0; c < 4; c++)
#pragma unroll
            for (int e = 0; e < 4; e++) acc[a][c][e] = 0.f;

    ldA(0); cpB(0, 0); stsA(0, 0);

    const int NK = 20;
    for (int ki = 0; ki < NK; ki++) {
        int cur = ki & 1;
        if (ki + 1 < NK) { ldA(ki + 1); cpB(ki + 1, cur ^ 1); cp_wait1(); } else { cp_wait0(); }
        __syncthreads();
        const uint32_t* Au = (const uint32_t*)(smem + offA[cur]);
        const uint32_t* Bu = (const uint32_t*)(smem + offB[cur]);
#pragma unroll
        for (int ks = 0; ks < 32; ks += 8) {
            uint32_t af[4][4];
#pragma unroll
            for (int mf = 0; mf < 4; mf++) {
                const uint32_t* p = Au + (wm0 + mf * 16 + grp) * SA + ks + lt4;
                af[mf][0] = p[0]; af[mf][1] = p[8 * SA];
                af[mf][2] = p[4]; af[mf][3] = p[8 * SA + 4];
            }
#pragma unroll
            for (int nf = 0; nf < 4; nf++) {
                const uint32_t* q = Bu + (wn0 + nf * 8 + grp) * SA + ks + lt4;
                uint32_t b0 = q[0], b1 = q[4];
#pragma unroll
                for (int mf = 0; mf < 4; mf++) mma8(acc[mf][nf], af[mf], b0, b1);
            }
        }
        if (ki + 1 < NK) stsA(ki + 1, cur ^ 1);
        __syncthreads();
    }

    float* bounce = (float*)(smem + 8192);
#pragma unroll
    for (int mf = 0; mf < 4; mf++) {
        int r = wm0 + mf * 16 + grp;
#pragma unroll
        for (int nf = 0; nf < 4; nf++) {
            int c = wn0 + nf * 8 + 2 * lt4;
            bounce[(c + 0) * 132 + r] = acc[mf][nf][0];
            bounce[(c + 1) * 132 + r] = acc[mf][nf][1];
            bounce[(c + 0) * 132 + r + 8] = acc[mf][nf][2];
            bounce[(c + 1) * 132 + r + 8] = acc[mf][nf][3];
        }
    }
    __syncthreads();
#pragma unroll
    for (int pass = 0; pass < 16; pass++) {
        int c = pass * 8 + (tid >> 5);
        int cg = n0 + c;
        float4 v = *(const float4*)&bounce[c * 132 + lane * 4];
        size_t idx = ((size_t)b * 256 + cg) * 32768 + s0 + lane * 4;
        float4 xv = *(const float4*)(x + idx);
        float bb = bo[cg];
        v.x += xv.x + bb; v.y += xv.y + bb; v.z += xv.z + bb; v.w += xv.w + bb;
        *(float4*)(out + idx) = v;
    }
}

// ---------------- launch ----------------
extern "C" void kernel_launch(void* const* d_in, const int* in_sizes, int n_in,
                              void* d_out, int out_size) {
    const float* x   = (const float*)d_in[0];
    const float* ctx = (const float*)d_in[1];
    const float* gng = (const float*)d_in[2];
    const float* gnb = (const float*)d_in[3];
    const float* lng = (const float*)d_in[4];
    const float* lnb = (const float*)d_in[5];
    const float* Wq  = (const float*)d_in[6];
    const float* Wk  = (const float*)d_in[7];
    const float* Wv  = (const float*)d_in[8];
    const float* Wo  = (const float*)d_in[9];
    const float* bo  = (const float*)d_in[10];
    float* out = (float*)d_out;

    cudaFuncSetAttribute(gemm1_mma, cudaFuncAttributeMaxDynamicSharedMemorySize, 73728);
    cudaFuncSetAttribute(gemm2_mma, cudaFuncAttributeMaxDynamicSharedMemorySize, 81920);

    gn_partial_k<<<1024, 256>>>(x);
    gn_final_k<<<16, 32>>>();
    xt_k<<<dim3(1024, 8, 2), dim3(32, 8)>>>(x, gng, gnb);
    ctx_ln_k<<<154, 256>>>(ctx, lng, lnb);
    kv_proj_k<<<dim3(4, 154), 128>>>(Wk, Wv);
    make_kp_k<<<dim3(NP, NB), 256>>>(Wq);
    make_vw_k<<<dim3(NP, NB), 256>>>(Wo);
    gemm1_mma<<<dim3(5, 512), 256, 73728>>>();
    rowstat_k<<<8192, 256>>>();
    gemm2_mma<<<dim3(2, 512), 256, 81920>>>(x, bo, out);
}

// round 6
// speedup vs baseline: 2.6064x; 1.2332x over previous
#include <cuda_runtime.h>
#include <cuda_fp16.h>
#include <math.h>
#include <stdint.h>

#define NB 2
#define NC 256
#define NS 32768
#define CTX 77
#define HEADS 8
#define JP 80
#define NP 640
#define M_TOTAL 65536
#define EPS 1e-5f
#define ATT_SCALE 0.17677669529663687f

// ---------------- scratch ----------------
__device__ float g_part[1024][2];
__device__ float g_stat[16][2];
__device__ float g_cn[NB * CTX * 768];
__device__ float g_k[NB * HEADS * CTX * 32];
__device__ float g_v[NB * HEADS * CTX * 32];
__device__ __half g_kp[NB * NP * NC];             // B1: [b][n][k=c]
__device__ __half g_vw[NB * NC * NP];             // B2: [b][c][k=np]
__device__ __half g_xt[(size_t)M_TOTAL * NC];     // A1: [row][c]
__device__ float g_s[(size_t)M_TOTAL * NP];       // logits (fp32)
__device__ float g_rs[(size_t)M_TOTAL * 16];      // per (row,head): max, 1/sum

// ---------------- helpers ----------------
__device__ __forceinline__ uint32_t smem_u32(const void* p) {
    uint32_t a;
    asm("{ .reg .u64 t; cvta.to.shared.u64 t, %1; cvt.u32.u64 %0, t; }" : "=r"(a) : "l"(p));
    return a;
}
__device__ __forceinline__ void cp16(uint32_t dst, const void* src) {
    asm volatile("cp.async.ca.shared.global [%0], [%1], 16;" :: "r"(dst), "l"(src));
}
__device__ __forceinline__ void cp_commit() { asm volatile("cp.async.commit_group;" ::: "memory"); }
__device__ __forceinline__ void cp_wait0() { asm volatile("cp.async.wait_group 0;" ::: "memory"); }
__device__ __forceinline__ void cp_wait1() { asm volatile("cp.async.wait_group 1;" ::: "memory"); }

__device__ __forceinline__ void mma16(float* c, const uint32_t* a, uint32_t b0, uint32_t b1) {
    asm volatile("mma.sync.aligned.m16n8k16.row.col.f32.f16.f16.f32 "
                 "{%0,%1,%2,%3},{%4,%5,%6,%7},{%8,%9},{%0,%1,%2,%3};"
                 : "+f"(c[0]), "+f"(c[1]), "+f"(c[2]), "+f"(c[3])
                 : "r"(a[0]), "r"(a[1]), "r"(a[2]), "r"(a[3]), "r"(b0), "r"(b1));
}
__device__ __forceinline__ void ldsm4(uint32_t* r, uint32_t addr) {
    asm volatile("ldmatrix.sync.aligned.m8n8.x4.shared.b16 {%0,%1,%2,%3}, [%4];"
                 : "=r"(r[0]), "=r"(r[1]), "=r"(r[2]), "=r"(r[3]) : "r"(addr));
}

#define SH 40                       // smem row stride in halves (80B)
#define TILE_BYTES (128 * SH * 2)   // 10240 B per operand buffer

// ---------------- groupnorm stats ----------------
__global__ void gn_partial_k(const float* __restrict__ x) {
    int tid = threadIdx.x, blk = blockIdx.x;
    const float4* p = (const float4*)x + (size_t)blk * 4096;
    float s = 0.f, sq = 0.f;
#pragma unroll
    for (int i = 0; i < 16; i++) {
        float4 v = p[i * 256 + tid];
        s += v.x + v.y + v.z + v.w;
        sq += v.x * v.x + v.y * v.y + v.z * v.z + v.w * v.w;
    }
#pragma unroll
    for (int o = 16; o; o >>= 1) {
        s += __shfl_xor_sync(0xffffffffu, s, o);
        sq += __shfl_xor_sync(0xffffffffu, sq, o);
    }
    __shared__ float r[8][2];
    if ((tid & 31) == 0) { r[tid >> 5][0] = s; r[tid >> 5][1] = sq; }
    __syncthreads();
    if (tid == 0) {
        float ts = 0.f, tq = 0.f;
#pragma unroll
        for (int i = 0; i < 8; i++) { ts += r[i][0]; tq += r[i][1]; }
        g_part[blk][0] = ts; g_part[blk][1] = tq;
    }
}

__global__ void gn_final_k() {
    int gi = blockIdx.x, t = threadIdx.x;
    float s = g_part[gi * 64 + t][0] + g_part[gi * 64 + 32 + t][0];
    float sq = g_part[gi * 64 + t][1] + g_part[gi * 64 + 32 + t][1];
#pragma unroll
    for (int o = 16; o; o >>= 1) {
        s += __shfl_xor_sync(0xffffffffu, s, o);
        sq += __shfl_xor_sync(0xffffffffu, sq, o);
    }
    if (t == 0) {
        const float inv = 1.f / 1048576.f;
        float mean = s * inv;
        float var = sq * inv - mean * mean;
        g_stat[gi][0] = mean;
        g_stat[gi][1] = rsqrtf(var + EPS);
    }
}

// ---------------- transpose + GN affine -> fp16 ----------------
__global__ void xt_k(const float* __restrict__ x, const float* __restrict__ gng,
                     const float* __restrict__ gnb) {
    __shared__ float tl[32][33];
    __shared__ float a32[32], b32[32];
    int tx = threadIdx.x, ty = threadIdx.y;
    int s0 = blockIdx.x * 32, c0 = blockIdx.y * 32, b = blockIdx.z;
    if (ty == 0) {
        int c = c0 + tx, g = c >> 5;
        float mean = g_stat[b * 8 + g][0], rstd = g_stat[b * 8 + g][1];
        float ga = gng[c];
        a32[tx] = rstd * ga;
        b32[tx] = gnb[c] - mean * rstd * ga;
    }
#pragma unroll
    for (int i = ty; i < 32; i += 8)
        tl[i][tx] = x[((size_t)b * 256 + c0 + i) * 32768 + s0 + tx];
    __syncthreads();
#pragma unroll
    for (int i = ty; i < 32; i += 8) {
        float v = tl[tx][i] * a32[tx] + b32[tx];
        g_xt[((size_t)b * 32768 + s0 + i) * 256 + c0 + tx] = __float2half(v);
    }
}

// ---------------- context LayerNorm ----------------
__global__ void ctx_ln_k(const float* __restrict__ ctx, const float* __restrict__ lng,
                         const float* __restrict__ lnb) {
    __shared__ float red[8][2];
    __shared__ float smean, srstd;
    int row = blockIdx.x, tid = threadIdx.x;
    const float* cp = ctx + (size_t)row * 768;
    float v[3]; float s = 0.f, sq = 0.f;
#pragma unroll
    for (int i = 0; i < 3; i++) { v[i] = cp[tid + i * 256]; s += v[i]; sq += v[i] * v[i]; }
#pragma unroll
    for (int o = 16; o; o >>= 1) {
        s += __shfl_xor_sync(0xffffffffu, s, o);
        sq += __shfl_xor_sync(0xffffffffu, sq, o);
    }
    if ((tid & 31) == 0) { red[tid >> 5][0] = s; red[tid >> 5][1] = sq; }
    __syncthreads();
    if (tid == 0) {
        float ts = 0.f, tq = 0.f;
#pragma unroll
        for (int i = 0; i < 8; i++) { ts += red[i][0]; tq += red[i][1]; }
        float mean = ts * (1.f / 768.f);
        float var = tq * (1.f / 768.f) - mean * mean;
        smean = mean; srstd = rsqrtf(var + EPS);
    }
    __syncthreads();
    float mean = smean, rstd = srstd;
#pragma unroll
    for (int i = 0; i < 3; i++) {
        int idx = tid + i * 256;
        g_cn[(size_t)row * 768 + idx] = (v[i] - mean) * rstd * lng[idx] + lnb[idx];
    }
}

// ---------------- K,V projection ----------------
__global__ void kv_proj_k(const float* __restrict__ Wk, const float* __restrict__ Wv) {
    __shared__ float xn[768];
    int tid = threadIdx.x, row = blockIdx.y;
#pragma unroll
    for (int i = 0; i < 6; i++) xn[tid + i * 128] = g_cn[(size_t)row * 768 + tid + i * 128];
    __syncthreads();
    int isV = tid >> 6;
    int c = blockIdx.x * 64 + (tid & 63);
    const float* W = isV ? Wv : Wk;
    float acc = 0.f;
#pragma unroll 16
    for (int i = 0; i < 768; i++) acc += xn[i] * W[i * 256 + c];
    int b = row / 77, j = row % 77, h = c >> 5, d = c & 31;
    size_t o = (((size_t)b * HEADS + h) * CTX + j) * 32 + d;
    if (isV) g_v[o] = acc;
    else g_k[o] = acc * ATT_SCALE;
}

// ---------------- K'[b][n][k=c] fp16 ----------------
__global__ void make_kp_k(const float* __restrict__ Wq) {
    int n = blockIdx.x, b = blockIdx.y, c = threadIdx.x;
    int h = n / JP, j = n % JP;
    __shared__ float wq[256][33];
    __shared__ float ks[32];
#pragma unroll
    for (int i = 0; i < 32; i++) {
        int r = i * 8 + (c >> 5); int d = c & 31;
        wq[r][d] = Wq[r * 256 + h * 32 + d];
    }
    if (c < 32 && j < CTX) ks[c] = g_k[(((size_t)b * HEADS + h) * CTX + j) * 32 + c];
    __syncthreads();
    float acc = 0.f;
    if (j < CTX) {
#pragma unroll
        for (int d = 0; d < 32; d++) acc += wq[c][d] * ks[d];
    }
    g_kp[((size_t)b * NP + n) * NC + c] = __float2half(acc);
}

// ---------------- VW[b][c][k=np] fp16 ----------------
__global__ void make_vw_k(const float* __restrict__ Wo) {
    int n = blockIdx.x, b = blockIdx.y, c = threadIdx.x;
    int h = n / JP, j = n % JP;
    __shared__ float vs[32];
    if (c < 32 && j < CTX) vs[c] = g_v[(((size_t)b * HEADS + h) * CTX + j) * 32 + c];
    __syncthreads();
    float acc = 0.f;
    if (j < CTX) {
#pragma unroll
        for (int d = 0; d < 32; d++) acc += vs[d] * Wo[(h * 32 + d) * 256 + c];
    }
    g_vw[((size_t)b * NC + c) * NP + n] = __float2half(acc);
}

// ---------------- GEMM1: fp16 mma + ldmatrix ----------------
__global__ void __launch_bounds__(256) gemm1_mma() {
    extern __shared__ char smem[];
    uint32_t sb = smem_u32(smem);
    int tid = threadIdx.x, lane = tid & 31, wid = tid >> 5;
    int grp = lane >> 2, lt4 = lane & 3;
    int wm0 = (wid & 1) * 64, wn0 = (wid >> 1) * 32;
    int n0 = blockIdx.x * 128;
    int row0 = blockIdx.y * 128;
    int b = row0 >> 15;

    const __half* Ag = g_xt + (size_t)row0 * 256;
    const __half* Bg = g_kp + ((size_t)b * NP + n0) * 256;

    const uint32_t offA[2] = {0u, 2u * TILE_BYTES};
    const uint32_t offB[2] = {TILE_BYTES, 3u * TILE_BYTES};

    int sm = tid >> 1;
    int so = (tid & 1) * 16;
    uint32_t dstoff = (uint32_t)(sm * SH + so) * 2u;

    auto stage = [&](int ki, int buf) {
        const __half* a = Ag + (size_t)sm * 256 + ki * 32 + so;
        const __half* bp = Bg + (size_t)sm * 256 + ki * 32 + so;
        cp16(sb + offA[buf] + dstoff, a);
        cp16(sb + offA[buf] + dstoff + 16, a + 8);
        cp16(sb + offB[buf] + dstoff, bp);
        cp16(sb + offB[buf] + dstoff + 16, bp + 8);
        cp_commit();
    };

    uint32_t lrow = (uint32_t)(lane & 15);
    uint32_t lcol = (uint32_t)((lane >> 4) << 3);
    uint32_t aoff[4], boff[2];
#pragma unroll
    for (int mf = 0; mf < 4; mf++)
        aoff[mf] = ((wm0 + mf * 16 + lrow) * SH + lcol) * 2u;
#pragma unroll
    for (int nfp = 0; nfp < 2; nfp++)
        boff[nfp] = ((wn0 + nfp * 16 + lrow) * SH + lcol) * 2u;

    float acc[4][4][4];
#pragma unroll
    for (int a = 0; a < 4; a++)
#pragma unroll
        for (int c = 0; c < 4; c++)
#pragma unroll
            for (int e = 0; e < 4; e++) acc[a][c][e] = 0.f;

    stage(0, 0);
    const int NK = 8;
    for (int ki = 0; ki < NK; ki++) {
        int cur = ki & 1;
        if (ki + 1 < NK) { stage(ki + 1, cur ^ 1); cp_wait1(); } else { cp_wait0(); }
        __syncthreads();
        uint32_t bA = sb + offA[cur], bB = sb + offB[cur];
#pragma unroll
        for (int kk = 0; kk < 32; kk += 16) {
            uint32_t af[4][4], bbf[2][4];
#pragma unroll
            for (int mf = 0; mf < 4; mf++) ldsm4(af[mf], bA + aoff[mf] + kk * 2);
#pragma unroll
            for (int nfp = 0; nfp < 2; nfp++) ldsm4(bbf[nfp], bB + boff[nfp] + kk * 2);
#pragma unroll
            for (int nf = 0; nf < 4; nf++) {
                uint32_t b0 = bbf[nf >> 1][nf & 1], b1 = bbf[nf >> 1][2 + (nf & 1)];
#pragma unroll
                for (int mf = 0; mf < 4; mf++) mma16(acc[mf][nf], af[mf], b0, b1);
            }
        }
        __syncthreads();
    }

#pragma unroll
    for (int mf = 0; mf < 4; mf++) {
        int r = row0 + wm0 + mf * 16 + grp;
#pragma unroll
        for (int nf = 0; nf < 4; nf++) {
            int c = n0 + wn0 + nf * 8 + 2 * lt4;
            *(float2*)&g_s[(size_t)r * NP + c] = make_float2(acc[mf][nf][0], acc[mf][nf][1]);
            *(float2*)&g_s[(size_t)(r + 8) * NP + c] = make_float2(acc[mf][nf][2], acc[mf][nf][3]);
        }
    }
}

// ---------------- row stats ----------------
__global__ void rowstat_k() {
    int warp = threadIdx.x >> 5, lane = threadIdx.x & 31;
#pragma unroll
    for (int it = 0; it < 8; it++) {
        int task = blockIdx.x * 64 + warp * 8 + it;
        int row = task >> 3, h = task & 7;
        const float* p = &g_s[(size_t)row * NP + h * JP];
        float v0 = p[lane];
        float v1 = p[lane + 32];
        float v2 = (lane < 13) ? p[lane + 64] : -1e30f;
        float m = fmaxf(v0, fmaxf(v1, v2));
#pragma unroll
        for (int o = 16; o; o >>= 1) m = fmaxf(m, __shfl_xor_sync(0xffffffffu, m, o));
        float s = __expf(v0 - m) + __expf(v1 - m) + ((lane < 13) ? __expf(v2 - m) : 0.f);
#pragma unroll
        for (int o = 16; o; o >>= 1) s += __shfl_xor_sync(0xffffffffu, s, o);
        if (lane == 0)
            *(float2*)&g_rs[(size_t)row * 16 + h * 2] = make_float2(m, 1.f / s);
    }
}

// ---------------- GEMM2: fp16 mma + ldmatrix, softmax fused in A-stage ----------------
__global__ void __launch_bounds__(256) gemm2_mma(const float* __restrict__ x,
                                                 const float* __restrict__ bo,
                                                 float* __restrict__ out) {
    extern __shared__ char smem[];
    uint32_t sb = smem_u32(smem);
    int tid = threadIdx.x, lane = tid & 31, wid = tid >> 5;
    int grp = lane >> 2, lt4 = lane & 3;
    int wm0 = (wid & 1) * 64, wn0 = (wid >> 1) * 32;
    int n0 = blockIdx.x * 128;
    int row0 = blockIdx.y * 128;
    int b = row0 >> 15, s0 = row0 & 32767;

    float* sstat = (float*)smem;   // 8KB
    const uint32_t base = 8192u;
    const uint32_t offA[2] = {base, base + 2u * TILE_BYTES};
    const uint32_t offB[2] = {base + TILE_BYTES, base + 3u * TILE_BYTES};

#pragma unroll
    for (int i = 0; i < 8; i++)
        sstat[tid + i * 256] = g_rs[(size_t)row0 * 16 + tid + i * 256];
    __syncthreads();

    const float* Ag = g_s + (size_t)row0 * NP;
    const __half* Bg = g_vw + ((size_t)b * NC + n0) * NP;

    int sm = tid >> 1;
    int so = (tid & 1) * 16;
    uint32_t dstoff = (uint32_t)(sm * SH + so) * 2u;

    float4 ra[4];
    auto ldA = [&](int ki) {
        int kb = ki * 32 + so;
#pragma unroll
        for (int i = 0; i < 4; i++)
            ra[i] = *(const float4*)(Ag + (size_t)sm * NP + kb + i * 4);
    };
    auto stsA = [&](int ki, int buf) {
        int kb = ki * 32 + so;        // multiple of 16; lies in one head segment
        int h = kb / JP;
        int jj = kb - h * JP;
        float mx = sstat[sm * 16 + 2 * h];
        float iv = sstat[sm * 16 + 2 * h + 1];
        uint32_t u[8];
#pragma unroll
        for (int i = 0; i < 4; i++) {
            float4 v = ra[i];
            float e0 = (jj + i * 4 + 0 < CTX) ? __expf(v.x - mx) * iv : 0.f;
            float e1 = (jj + i * 4 + 1 < CTX) ? __expf(v.y - mx) * iv : 0.f;
            float e2 = (jj + i * 4 + 2 < CTX) ? __expf(v.z - mx) * iv : 0.f;
            float e3 = (jj + i * 4 + 3 < CTX) ? __expf(v.w - mx) * iv : 0.f;
            __half2 h0 = __floats2half2_rn(e0, e1);
            __half2 h1 = __floats2half2_rn(e2, e3);
            u[i * 2] = *(uint32_t*)&h0;
            u[i * 2 + 1] = *(uint32_t*)&h1;
        }
        char* dst = smem + offA[buf] + dstoff;
        *(uint4*)dst = make_uint4(u[0], u[1], u[2], u[3]);
        *(uint4*)(dst + 16) = make_uint4(u[4], u[5], u[6], u[7]);
    };
    auto cpB = [&](int ki, int buf) {
        const __half* bp = Bg + (size_t)sm * NP + ki * 32 + so;
        cp16(sb + offB[buf] + dstoff, bp);
        cp16(sb + offB[buf] + dstoff + 16, bp + 8);
        cp_commit();
    };

    uint32_t lrow = (uint32_t)(lane & 15);
    uint32_t lcol = (uint32_t)((lane >> 4) << 3);
    uint32_t aoff[4], boff[2];
#pragma unroll
    for (int mf = 0; mf < 4; mf++)
        aoff[mf] = ((wm0 + mf * 16 + lrow) * SH + lcol) * 2u;
#pragma unroll
    for (int nfp = 0; nfp < 2; nfp++)
        boff[nfp] = ((wn0 + nfp * 16 + lrow) * SH + lcol) * 2u;

    float acc[4][4][4];
#pragma unroll
    for (int a = 0; a < 4; a++)
#pragma unroll
        for (int c = 0; c < 4; c++)
#pragma unroll
            for (int e = 0; e < 4; e++) acc[a][c][e] = 0.f;

    ldA(0); cpB(0, 0); stsA(0, 0);

    const int NK = 20;
    for (int ki = 0; ki < NK; ki++) {
        int cur = ki & 1;
        if (ki + 1 < NK) { ldA(ki + 1); cpB(ki + 1, cur ^ 1); cp_wait1(); } else { cp_wait0(); }
        __syncthreads();
        uint32_t bA = sb + offA[cur], bB = sb + offB[cur];
#pragma unroll
        for (int kk = 0; kk < 32; kk += 16) {
            uint32_t af[4][4], bbf[2][4];
#pragma unroll
            for (int mf = 0; mf < 4; mf++) ldsm4(af[mf], bA + aoff[mf] + kk * 2);
#pragma unroll
            for (int nfp = 0; nfp < 2; nfp++) ldsm4(bbf[nfp], bB + boff[nfp] + kk * 2);
#pragma unroll
            for (int nf = 0; nf < 4; nf++) {
                uint32_t b0 = bbf[nf >> 1][nf & 1], b1 = bbf[nf >> 1][2 + (nf & 1)];
#pragma unroll
                for (int mf = 0; mf < 4; mf++) mma16(acc[mf][nf], af[mf], b0, b1);
            }
        }
        if (ki + 1 < NK) stsA(ki + 1, cur ^ 1);
        __syncthreads();
    }

    float* bounce = (float*)(smem + 8192);
#pragma unroll
    for (int mf = 0; mf < 4; mf++) {
        int r = wm0 + mf * 16 + grp;
#pragma unroll
        for (int nf = 0; nf < 4; nf++) {
            int c = wn0 + nf * 8 + 2 * lt4;
            bounce[(c + 0) * 132 + r] = acc[mf][nf][0];
            bounce[(c + 1) * 132 + r] = acc[mf][nf][1];
            bounce[(c + 0) * 132 + r + 8] = acc[mf][nf][2];
            bounce[(c + 1) * 132 + r + 8] = acc[mf][nf][3];
        }
    }
    __syncthreads();
#pragma unroll
    for (int pass = 0; pass < 16; pass++) {
        int c = pass * 8 + (tid >> 5);
        int cg = n0 + c;
        float4 v = *(const float4*)&bounce[c * 132 + lane * 4];
        size_t idx = ((size_t)b * 256 + cg) * 32768 + s0 + lane * 4;
        float4 xv = *(const float4*)(x + idx);
        float bb2 = bo[cg];
        v.x += xv.x + bb2; v.y += xv.y + bb2; v.z += xv.z + bb2; v.w += xv.w + bb2;
        *(float4*)(out + idx) = v;
    }
}

// ---------------- launch ----------------
extern "C" void kernel_launch(void* const* d_in, const int* in_sizes, int n_in,
                              void* d_out, int out_size) {
    const float* x   = (const float*)d_in[0];
    const float* ctx = (const float*)d_in[1];
    const float* gng = (const float*)d_in[2];
    const float* gnb = (const float*)d_in[3];
    const float* lng = (const float*)d_in[4];
    const float* lnb = (const float*)d_in[5];
    const float* Wq  = (const float*)d_in[6];
    const float* Wk  = (const float*)d_in[7];
    const float* Wv  = (const float*)d_in[8];
    const float* Wo  = (const float*)d_in[9];
    const float* bo  = (const float*)d_in[10];
    float* out = (float*)d_out;

    cudaFuncSetAttribute(gemm1_mma, cudaFuncAttributeMaxDynamicSharedMemorySize, 4 * TILE_BYTES);
    cudaFuncSetAttribute(gemm2_mma, cudaFuncAttributeMaxDynamicSharedMemorySize, 8192 + 128 * 132 * 4);

    gn_partial_k<<<1024, 256>>>(x);
    gn_final_k<<<16, 32>>>();
    xt_k<<<dim3(1024, 8, 2), dim3(32, 8)>>>(x, gng, gnb);
    ctx_ln_k<<<154, 256>>>(ctx, lng, lnb);
    kv_proj_k<<<dim3(4, 154), 128>>>(Wk, Wv);
    make_kp_k<<<dim3(NP, NB), 256>>>(Wq);
    make_vw_k<<<dim3(NP, NB), 256>>>(Wo);
    gemm1_mma<<<dim3(5, 512), 256, 4 * TILE_BYTES>>>();
    rowstat_k<<<8192, 256>>>();
    gemm2_mma<<<dim3(2, 512), 256, 8192 + 128 * 132 * 4>>>(x, bo, out);
}

// round 7
// speedup vs baseline: 3.4795x; 1.3350x over previous
#include <cuda_runtime.h>
#include <cuda_fp16.h>
#include <math.h>
#include <stdint.h>

#define NB 2
#define NC 256
#define NS 32768
#define CTX 77
#define HEADS 8
#define JP 80
#define NP 640
#define M_TOTAL 65536
#define EPS 1e-5f
#define ATT_SCALE 0.17677669529663687f

// ---------------- scratch ----------------
__device__ float g_part[16 * 1024 * 2];           // per-(b,g) per-s-block partials
__device__ float g_stat[16][2];                   // mean, rstd per (b*8+g)
__device__ float g_cn[NB * CTX * 768];
__device__ float g_k[NB * HEADS * CTX * 32];
__device__ float g_v[NB * HEADS * CTX * 32];
__device__ __half g_kp[NB * NP * NC];             // B1: [b][n][k=c], GN-scale folded
__device__ float g_sbias[NB * NP];                // GN additive part folded: bias[n]
__device__ __half g_vw[NB * NC * NP];             // B2: [b][c][k=np]
__device__ __half g_xt[(size_t)M_TOTAL * NC];     // A1: raw x^T fp16 [row][c]
__device__ __half g_p[(size_t)M_TOTAL * NP];      // softmax probabilities fp16

// ---------------- helpers ----------------
__device__ __forceinline__ uint32_t smem_u32(const void* p) {
    uint32_t a;
    asm("{ .reg .u64 t; cvta.to.shared.u64 t, %1; cvt.u32.u64 %0, t; }" : "=r"(a) : "l"(p));
    return a;
}
__device__ __forceinline__ void cp16(uint32_t dst, const void* src) {
    asm volatile("cp.async.ca.shared.global [%0], [%1], 16;" :: "r"(dst), "l"(src));
}
__device__ __forceinline__ void cp_commit() { asm volatile("cp.async.commit_group;" ::: "memory"); }
__device__ __forceinline__ void cp_wait0() { asm volatile("cp.async.wait_group 0;" ::: "memory"); }
__device__ __forceinline__ void cp_wait1() { asm volatile("cp.async.wait_group 1;" ::: "memory"); }

__device__ __forceinline__ void mma16(float* c, const uint32_t* a, uint32_t b0, uint32_t b1) {
    asm volatile("mma.sync.aligned.m16n8k16.row.col.f32.f16.f16.f32 "
                 "{%0,%1,%2,%3},{%4,%5,%6,%7},{%8,%9},{%0,%1,%2,%3};"
                 : "+f"(c[0]), "+f"(c[1]), "+f"(c[2]), "+f"(c[3])
                 : "r"(a[0]), "r"(a[1]), "r"(a[2]), "r"(a[3]), "r"(b0), "r"(b1));
}
__device__ __forceinline__ void ldsm4(uint32_t* r, uint32_t addr) {
    asm volatile("ldmatrix.sync.aligned.m8n8.x4.shared.b16 {%0,%1,%2,%3}, [%4];"
                 : "=r"(r[0]), "=r"(r[1]), "=r"(r[2]), "=r"(r[3]) : "r"(addr));
}

#define SH 40                         // smem row stride in halves (80B)
#define A_TILE_B (128 * SH * 2)       // 10240
#define B1_TILE_B (160 * SH * 2)      // 12800

// ---------------- xt_k: transpose x -> fp16 g_xt, fused GN partial stats ----------------
__global__ void xt_k(const float* __restrict__ x) {
    __shared__ float tl[32][33];
    __shared__ float red[8][2];
    int tx = threadIdx.x, ty = threadIdx.y;
    int s0 = blockIdx.x * 32, g = blockIdx.y, b = blockIdx.z;
    int c0 = g * 32;
    float s = 0.f, sq = 0.f;
#pragma unroll
    for (int i = ty; i < 32; i += 8) {
        float v = x[((size_t)b * 256 + c0 + i) * 32768 + s0 + tx];
        tl[i][tx] = v;
        s += v; sq += v * v;
    }
    __syncthreads();
#pragma unroll
    for (int i = ty; i < 32; i += 8)
        g_xt[((size_t)b * 32768 + s0 + i) * 256 + c0 + tx] = __float2half(tl[tx][i]);
    // block reduce stats
#pragma unroll
    for (int o = 16; o; o >>= 1) {
        s += __shfl_xor_sync(0xffffffffu, s, o);
        sq += __shfl_xor_sync(0xffffffffu, sq, o);
    }
    if (tx == 0) { red[ty][0] = s; red[ty][1] = sq; }
    __syncthreads();
    if (tx == 0 && ty == 0) {
        float ts = 0.f, tq = 0.f;
#pragma unroll
        for (int i = 0; i < 8; i++) { ts += red[i][0]; tq += red[i][1]; }
        int idx = ((b * 8 + g) * 1024 + blockIdx.x) * 2;
        g_part[idx] = ts; g_part[idx + 1] = tq;
    }
}

// ---------------- gn_final: reduce 1024 partials per (b,g) ----------------
__global__ void gn_final_k() {
    __shared__ float red[8][2];
    int gi = blockIdx.x, tid = threadIdx.x;
    float s = 0.f, sq = 0.f;
    for (int i = tid; i < 1024; i += 256) {
        float2 v = *(const float2*)&g_part[(gi * 1024 + i) * 2];
        s += v.x; sq += v.y;
    }
#pragma unroll
    for (int o = 16; o; o >>= 1) {
        s += __shfl_xor_sync(0xffffffffu, s, o);
        sq += __shfl_xor_sync(0xffffffffu, sq, o);
    }
    if ((tid & 31) == 0) { red[tid >> 5][0] = s; red[tid >> 5][1] = sq; }
    __syncthreads();
    if (tid == 0) {
        float ts = 0.f, tq = 0.f;
#pragma unroll
        for (int i = 0; i < 8; i++) { ts += red[i][0]; tq += red[i][1]; }
        const float inv = 1.f / 1048576.f;
        float mean = ts * inv;
        float var = tq * inv - mean * mean;
        g_stat[gi][0] = mean;
        g_stat[gi][1] = rsqrtf(var + EPS);
    }
}

// ---------------- context LayerNorm ----------------
__global__ void ctx_ln_k(const float* __restrict__ ctx, const float* __restrict__ lng,
                         const float* __restrict__ lnb) {
    __shared__ float red[8][2];
    __shared__ float smean, srstd;
    int row = blockIdx.x, tid = threadIdx.x;
    const float* cp = ctx + (size_t)row * 768;
    float v[3]; float s = 0.f, sq = 0.f;
#pragma unroll
    for (int i = 0; i < 3; i++) { v[i] = cp[tid + i * 256]; s += v[i]; sq += v[i] * v[i]; }
#pragma unroll
    for (int o = 16; o; o >>= 1) {
        s += __shfl_xor_sync(0xffffffffu, s, o);
        sq += __shfl_xor_sync(0xffffffffu, sq, o);
    }
    if ((tid & 31) == 0) { red[tid >> 5][0] = s; red[tid >> 5][1] = sq; }
    __syncthreads();
    if (tid == 0) {
        float ts = 0.f, tq = 0.f;
#pragma unroll
        for (int i = 0; i < 8; i++) { ts += red[i][0]; tq += red[i][1]; }
        float mean = ts * (1.f / 768.f);
        float var = tq * (1.f / 768.f) - mean * mean;
        smean = mean; srstd = rsqrtf(var + EPS);
    }
    __syncthreads();
    float mean = smean, rstd = srstd;
#pragma unroll
    for (int i = 0; i < 3; i++) {
        int idx = tid + i * 256;
        g_cn[(size_t)row * 768 + idx] = (v[i] - mean) * rstd * lng[idx] + lnb[idx];
    }
}

// ---------------- K,V projection ----------------
__global__ void kv_proj_k(const float* __restrict__ Wk, const float* __restrict__ Wv) {
    __shared__ float xn[768];
    int tid = threadIdx.x, row = blockIdx.y;
#pragma unroll
    for (int i = 0; i < 6; i++) xn[tid + i * 128] = g_cn[(size_t)row * 768 + tid + i * 128];
    __syncthreads();
    int isV = tid >> 6;
    int c = blockIdx.x * 64 + (tid & 63);
    const float* W = isV ? Wv : Wk;
    float acc = 0.f;
#pragma unroll 16
    for (int i = 0; i < 768; i++) acc += xn[i] * W[i * 256 + c];
    int b = row / 77, j = row % 77, h = c >> 5, d = c & 31;
    size_t o = (((size_t)b * HEADS + h) * CTX + j) * 32 + d;
    if (isV) g_v[o] = acc;
    else g_k[o] = acc * ATT_SCALE;
}

// ---------------- make_kp: K' with GN scale folded + bias vector ----------------
__global__ void make_kp_k(const float* __restrict__ Wq, const float* __restrict__ gng,
                          const float* __restrict__ gnb) {
    int n = blockIdx.x, b = blockIdx.y, c = threadIdx.x;
    int h = n / JP, j = n % JP;
    __shared__ float wq[256][33];
    __shared__ float ks[32];
    __shared__ float red[8];
#pragma unroll
    for (int i = 0; i < 32; i++) {
        int r = i * 8 + (c >> 5); int d = c & 31;
        wq[r][d] = Wq[r * 256 + h * 32 + d];
    }
    if (c < 32 && j < CTX) ks[c] = g_k[(((size_t)b * HEADS + h) * CTX + j) * 32 + c];
    __syncthreads();
    float acc = 0.f;
    if (j < CTX) {
#pragma unroll
        for (int d = 0; d < 32; d++) acc += wq[c][d] * ks[d];
    }
    int g = c >> 5;
    float mean = g_stat[b * 8 + g][0], rstd = g_stat[b * 8 + g][1];
    float ga = gng[c];
    float cA = rstd * ga;
    float cB = gnb[c] - mean * cA;
    g_kp[((size_t)b * NP + n) * NC + c] = __float2half(acc * cA);
    // bias[n] = sum_c cB[c] * Kp[n][c]
    float bc = cB * acc;
#pragma unroll
    for (int o = 16; o; o >>= 1) bc += __shfl_xor_sync(0xffffffffu, bc, o);
    if ((c & 31) == 0) red[c >> 5] = bc;
    __syncthreads();
    if (c == 0) {
        float t = 0.f;
#pragma unroll
        for (int i = 0; i < 8; i++) t += red[i];
        g_sbias[b * NP + n] = t;
    }
}

// ---------------- VW[b][c][k=np] fp16 ----------------
__global__ void make_vw_k(const float* __restrict__ Wo) {
    int n = blockIdx.x, b = blockIdx.y, c = threadIdx.x;
    int h = n / JP, j = n % JP;
    __shared__ float vs[32];
    if (c < 32 && j < CTX) vs[c] = g_v[(((size_t)b * HEADS + h) * CTX + j) * 32 + c];
    __syncthreads();
    float acc = 0.f;
    if (j < CTX) {
#pragma unroll
        for (int d = 0; d < 32; d++) acc += vs[d] * Wo[(h * 32 + d) * 256 + c];
    }
    g_vw[((size_t)b * NC + c) * NP + n] = __float2half(acc);
}

// ---------------- GEMM1 + fused softmax: g_p = softmax(x^T @ kp^T + bias) ----------------
// Tile 128 x 160 (= 2 heads), warps 4m x 2n: warp tile 32 x 80 = one full head.
__global__ void __launch_bounds__(256) gemm1_mma() {
    extern __shared__ char smem[];
    uint32_t sb = smem_u32(smem);
    int tid = threadIdx.x, lane = tid & 31, wid = tid >> 5;
    int grp = lane >> 2, lt4 = lane & 3;
    int wm0 = (wid & 3) * 32;
    int wn0 = (wid >> 2) * 80;         // head-local base within the 160 tile
    int n0 = blockIdx.x * 160;
    int row0 = blockIdx.y * 128;
    int b = row0 >> 15;

    const __half* Ag = g_xt + (size_t)row0 * 256;
    const __half* Bg = g_kp + ((size_t)b * NP + n0) * 256;

    const uint32_t offA[2] = {0u, (uint32_t)(A_TILE_B + B1_TILE_B)};
    const uint32_t offB[2] = {(uint32_t)A_TILE_B, (uint32_t)(2 * A_TILE_B + B1_TILE_B)};

    int sm = tid >> 1;
    int so = (tid & 1) * 16;
    uint32_t dstoff = (uint32_t)(sm * SH + so) * 2u;

    auto stage = [&](int ki, int buf) {
        const __half* a = Ag + (size_t)sm * 256 + ki * 32 + so;
        cp16(sb + offA[buf] + dstoff, a);
        cp16(sb + offA[buf] + dstoff + 16, a + 8);
        const __half* bp = Bg + (size_t)sm * 256 + ki * 32 + so;
        cp16(sb + offB[buf] + dstoff, bp);
        cp16(sb + offB[buf] + dstoff + 16, bp + 8);
        if (tid < 64) {   // B rows 128..159
            int r2 = 128 + (tid >> 1);
            const __half* bp2 = Bg + (size_t)r2 * 256 + ki * 32 + so;
            uint32_t d2 = (uint32_t)(r2 * SH + so) * 2u;
            cp16(sb + offB[buf] + d2, bp2);
            cp16(sb + offB[buf] + d2 + 16, bp2 + 8);
        }
        cp_commit();
    };

    uint32_t lrow = (uint32_t)(lane & 15);
    uint32_t lcol = (uint32_t)((lane >> 4) << 3);
    uint32_t aoff[2], boff[5];
#pragma unroll
    for (int mf = 0; mf < 2; mf++)
        aoff[mf] = ((wm0 + mf * 16 + lrow) * SH + lcol) * 2u;
#pragma unroll
    for (int nfp = 0; nfp < 5; nfp++)
        boff[nfp] = ((wn0 + nfp * 16 + lrow) * SH + lcol) * 2u;

    float acc[2][10][4];
#pragma unroll
    for (int a = 0; a < 2; a++)
#pragma unroll
        for (int c = 0; c < 10; c++)
#pragma unroll
            for (int e = 0; e < 4; e++) acc[a][c][e] = 0.f;

    stage(0, 0);
    const int NK = 8;
    for (int ki = 0; ki < NK; ki++) {
        int cur = ki & 1;
        if (ki + 1 < NK) { stage(ki + 1, cur ^ 1); cp_wait1(); } else { cp_wait0(); }
        __syncthreads();
        uint32_t bA = sb + offA[cur], bB = sb + offB[cur];
#pragma unroll
        for (int kk = 0; kk < 32; kk += 16) {
            uint32_t af[2][4], bbf[5][4];
#pragma unroll
            for (int mf = 0; mf < 2; mf++) ldsm4(af[mf], bA + aoff[mf] + kk * 2);
#pragma unroll
            for (int nfp = 0; nfp < 5; nfp++) ldsm4(bbf[nfp], bB + boff[nfp] + kk * 2);
#pragma unroll
            for (int nf = 0; nf < 10; nf++) {
                uint32_t b0 = bbf[nf >> 1][nf & 1], b1 = bbf[nf >> 1][2 + (nf & 1)];
#pragma unroll
                for (int mf = 0; mf < 2; mf++) mma16(acc[mf][nf], af[mf], b0, b1);
            }
        }
        __syncthreads();
    }

    // ---- fused softmax epilogue: warp owns rows [wm0, wm0+32) x one head ----
    int hglob = n0 + wn0;             // global n base of this warp's head
    float bias[10][2];
#pragma unroll
    for (int nf = 0; nf < 10; nf++) {
        float2 bv = *(const float2*)&g_sbias[b * NP + hglob + nf * 8 + 2 * lt4];
        bias[nf][0] = bv.x; bias[nf][1] = bv.y;
    }
#pragma unroll
    for (int mf = 0; mf < 2; mf++) {
#pragma unroll
        for (int rh = 0; rh < 2; rh++) {
            int row = wm0 + mf * 16 + grp + rh * 8;
            // logits with bias; pads -> -inf
            float m = -1e30f;
#pragma unroll
            for (int nf = 0; nf < 10; nf++) {
#pragma unroll
                for (int e = 0; e < 2; e++) {
                    int j = nf * 8 + 2 * lt4 + e;
                    float v = (j < CTX) ? acc[mf][nf][rh * 2 + e] + bias[nf][e] : -1e30f;
                    acc[mf][nf][rh * 2 + e] = v;
                    m = fmaxf(m, v);
                }
            }
            m = fmaxf(m, __shfl_xor_sync(0xffffffffu, m, 1));
            m = fmaxf(m, __shfl_xor_sync(0xffffffffu, m, 2));
            float s = 0.f;
#pragma unroll
            for (int nf = 0; nf < 10; nf++) {
#pragma unroll
                for (int e = 0; e < 2; e++) {
                    int j = nf * 8 + 2 * lt4 + e;
                    float ev = (j < CTX) ? __expf(acc[mf][nf][rh * 2 + e] - m) : 0.f;
                    acc[mf][nf][rh * 2 + e] = ev;
                    s += ev;
                }
            }
            s += __shfl_xor_sync(0xffffffffu, s, 1);
            s += __shfl_xor_sync(0xffffffffu, s, 2);
            float inv = 1.f / s;
            __half* pr = g_p + (size_t)(row0 + row) * NP + hglob + 2 * lt4;
#pragma unroll
            for (int nf = 0; nf < 10; nf++) {
                __half2 hv = __floats2half2_rn(acc[mf][nf][rh * 2] * inv,
                                               acc[mf][nf][rh * 2 + 1] * inv);
                *(__half2*)(pr + nf * 8) = hv;
            }
        }
    }
}

// ---------------- GEMM2: out = g_p @ vw^T + bo + x ----------------
__global__ void __launch_bounds__(256) gemm2_mma(const float* __restrict__ x,
                                                 const float* __restrict__ bo,
                                                 float* __restrict__ out) {
    extern __shared__ char smem[];
    uint32_t sb = smem_u32(smem);
    int tid = threadIdx.x, lane = tid & 31, wid = tid >> 5;
    int grp = lane >> 2, lt4 = lane & 3;
    int wm0 = (wid & 1) * 64, wn0 = (wid >> 1) * 32;
    int n0 = blockIdx.x * 128;
    int row0 = blockIdx.y * 128;
    int b = row0 >> 15, s0 = row0 & 32767;

    const uint32_t offA[2] = {0u, 2u * A_TILE_B};
    const uint32_t offB[2] = {(uint32_t)A_TILE_B, 3u * A_TILE_B};

    const __half* Ag = g_p + (size_t)row0 * NP;
    const __half* Bg = g_vw + ((size_t)b * NC + n0) * NP;

    int sm = tid >> 1;
    int so = (tid & 1) * 16;
    uint32_t dstoff = (uint32_t)(sm * SH + so) * 2u;

    auto stage = [&](int ki, int buf) {
        const __half* a = Ag + (size_t)sm * NP + ki * 32 + so;
        cp16(sb + offA[buf] + dstoff, a);
        cp16(sb + offA[buf] + dstoff + 16, a + 8);
        const __half* bp = Bg + (size_t)sm * NP + ki * 32 + so;
        cp16(sb + offB[buf] + dstoff, bp);
        cp16(sb + offB[buf] + dstoff + 16, bp + 8);
        cp_commit();
    };

    uint32_t lrow = (uint32_t)(lane & 15);
    uint32_t lcol = (uint32_t)((lane >> 4) << 3);
    uint32_t aoff[4], boff[2];
#pragma unroll
    for (int mf = 0; mf < 4; mf++)
        aoff[mf] = ((wm0 + mf * 16 + lrow) * SH + lcol) * 2u;
#pragma unroll
    for (int nfp = 0; nfp < 2; nfp++)
        boff[nfp] = ((wn0 + nfp * 16 + lrow) * SH + lcol) * 2u;

    float acc[4][4][4];
#pragma unroll
    for (int a = 0; a < 4; a++)
#pragma unroll
        for (int c = 0; c < 4; c++)
#pragma unroll
            for (int e = 0; e < 4; e++) acc[a][c][e] = 0.f;

    stage(0, 0);
    const int NK = 20;
    for (int ki = 0; ki < NK; ki++) {
        int cur = ki & 1;
        if (ki + 1 < NK) { stage(ki + 1, cur ^ 1); cp_wait1(); } else { cp_wait0(); }
        __syncthreads();
        uint32_t bA = sb + offA[cur], bB = sb + offB[cur];
#pragma unroll
        for (int kk = 0; kk < 32; kk += 16) {
            uint32_t af[4][4], bbf[2][4];
#pragma unroll
            for (int mf = 0; mf < 4; mf++) ldsm4(af[mf], bA + aoff[mf] + kk * 2);
#pragma unroll
            for (int nfp = 0; nfp < 2; nfp++) ldsm4(bbf[nfp], bB + boff[nfp] + kk * 2);
#pragma unroll
            for (int nf = 0; nf < 4; nf++) {
                uint32_t b0 = bbf[nf >> 1][nf & 1], b1 = bbf[nf >> 1][2 + (nf & 1)];
#pragma unroll
                for (int mf = 0; mf < 4; mf++) mma16(acc[mf][nf], af[mf], b0, b1);
            }
        }
        __syncthreads();
    }

    // epilogue: transpose via smem bounce, fused bias + residual
    float* bounce = (float*)smem;
#pragma unroll
    for (int mf = 0; mf < 4; mf++) {
        int r = wm0 + mf * 16 + grp;
#pragma unroll
        for (int nf = 0; nf < 4; nf++) {
            int c = wn0 + nf * 8 + 2 * lt4;
            bounce[(c + 0) * 132 + r] = acc[mf][nf][0];
            bounce[(c + 1) * 132 + r] = acc[mf][nf][1];
            bounce[(c + 0) * 132 + r + 8] = acc[mf][nf][2];
            bounce[(c + 1) * 132 + r + 8] = acc[mf][nf][3];
        }
    }
    __syncthreads();
#pragma unroll
    for (int pass = 0; pass < 16; pass++) {
        int c = pass * 8 + (tid >> 5);
        int cg = n0 + c;
        float4 v = *(const float4*)&bounce[c * 132 + lane * 4];
        size_t idx = ((size_t)b * 256 + cg) * 32768 + s0 + lane * 4;
        float4 xv = *(const float4*)(x + idx);
        float bb2 = bo[cg];
        v.x += xv.x + bb2; v.y += xv.y + bb2; v.z += xv.z + bb2; v.w += xv.w + bb2;
        *(float4*)(out + idx) = v;
    }
}

// ---------------- launch ----------------
extern "C" void kernel_launch(void* const* d_in, const int* in_sizes, int n_in,
                              void* d_out, int out_size) {
    const float* x   = (const float*)d_in[0];
    const float* ctx = (const float*)d_in[1];
    const float* gng = (const float*)d_in[2];
    const float* gnb = (const float*)d_in[3];
    const float* lng = (const float*)d_in[4];
    const float* lnb = (const float*)d_in[5];
    const float* Wq  = (const float*)d_in[6];
    const float* Wk  = (const float*)d_in[7];
    const float* Wv  = (const float*)d_in[8];
    const float* Wo  = (const float*)d_in[9];
    const float* bo  = (const float*)d_in[10];
    float* out = (float*)d_out;

    const int smem1 = 2 * (A_TILE_B + B1_TILE_B);   // 46080
    const int smem2 = 128 * 132 * 4;                // 67584 (> 4*A_TILE_B operand area)
    cudaFuncSetAttribute(gemm1_mma, cudaFuncAttributeMaxDynamicSharedMemorySize, smem1);
    cudaFuncSetAttribute(gemm2_mma, cudaFuncAttributeMaxDynamicSharedMemorySize, smem2);

    xt_k<<<dim3(1024, 8, 2), dim3(32, 8)>>>(x);
    gn_final_k<<<16, 256>>>();
    ctx_ln_k<<<154, 256>>>(ctx, lng, lnb);
    kv_proj_k<<<dim3(4, 154), 128>>>(Wk, Wv);
    make_kp_k<<<dim3(NP, NB), 256>>>(Wq, gng, gnb);
    make_vw_k<<<dim3(NP, NB), 256>>>(Wo);
    gemm1_mma<<<dim3(4, 512), 256, smem1>>>();
    gemm2_mma<<<dim3(2, 512), 256, smem2>>>(x, bo, out);
}